// round 5
// baseline (speedup 1.0000x reference)
#include <cuda_runtime.h>
#include <math_constants.h>

#define Bsz 4
#define Nn 1024
#define Dd 1024
#define Hh 16
#define QKd 64
#define HIDd 4096
#define BH 64           // B*H
#define BNr 4096        // B*N
#define HQ 1024         // H*QK
#define BETA 0.125f

// -------- device scratch (static allocation; no cudaMalloc anywhere) --------
__device__ float  g_Q  [(size_t)BH * Nn * QKd];   // [bh][n][qk]
__device__ float  g_K  [(size_t)BH * Nn * QKd];
__device__ float  g_dQ [(size_t)BH * Nn * QKd];
__device__ float  g_dK [(size_t)BH * Nn * QKd];
__device__ float  g_dQm[(size_t)BNr * HQ];        // [b*n][h*qk]
__device__ float  g_dKm[(size_t)BNr * HQ];
__device__ float  g_S  [(size_t)BH * Nn * Nn];    // scores, then exp'ed probs (256MB)
__device__ float  g_rowmax[BH * Nn];
__device__ float  g_inv  [BH * Nn];
__device__ float  g_Hb [(size_t)BNr * HIDd];      // relu(x @ W_hop)
__device__ double g_lse_part[BH * (Nn / 16)];     // 4096
__device__ double g_h2_part [(BNr / 128) * (HIDd / 128)]; // 1024

// ============================================================================
// Generic 128x128x8 SGEMM, 256 threads, 8x8 micro-tile.
//   TB=1:     C[m,n] = sum_k A[m,k] * B[n,k]   (B row-major [Ncols, Kd])
//   TB=0:     C[m,n] = sum_k A[m,k] * B[k,n]   (B row-major [Kd, Ncols])
//   SCATTER:  write C into [bh][n][qk] layout (forward Q/K projections)
//   RELU:     v = max(v,0); store; accumulate sum(v^2) per block into part[]
//   else:     C = alpha*acc  or  C += alpha*acc  (accFlag)
// ============================================================================
template<int TB, int SCATTER, int RELU>
__global__ void __launch_bounds__(256) sgemm_k(
    const float* __restrict__ A, const float* __restrict__ B, float* __restrict__ C,
    int M, int Ncols, int Kd, float alpha, int accFlag, double* __restrict__ part)
{
    __shared__ float As[8][132];
    __shared__ float Bs[8][132];
    const int t  = threadIdx.x;
    const int m0 = blockIdx.y * 128;
    const int n0 = blockIdx.x * 128;
    const int tr = t >> 4;
    const int tc = t & 15;
    const int lrow = t >> 1;          // 0..127
    const int lk4  = (t & 1) * 4;     // 0 or 4
    const int lbk  = t >> 5;          // 0..7
    const int lbn4 = (t & 31) * 4;    // 0..124

    float acc[8][8] = {};

    const float* Aptr = A + (size_t)(m0 + lrow) * Kd + lk4;
    const float* Bptr = TB ? (B + (size_t)(n0 + lrow) * Kd + lk4)
                           : (B + (size_t)lbk * Ncols + n0 + lbn4);

    for (int kt = 0; kt < Kd; kt += 8) {
        float4 av = *(const float4*)(Aptr + kt);
        As[lk4 + 0][lrow] = av.x; As[lk4 + 1][lrow] = av.y;
        As[lk4 + 2][lrow] = av.z; As[lk4 + 3][lrow] = av.w;
        if (TB) {
            float4 bv = *(const float4*)(Bptr + kt);
            Bs[lk4 + 0][lrow] = bv.x; Bs[lk4 + 1][lrow] = bv.y;
            Bs[lk4 + 2][lrow] = bv.z; Bs[lk4 + 3][lrow] = bv.w;
        } else {
            float4 bv = *(const float4*)(Bptr + (size_t)kt * Ncols);
            *(float4*)&Bs[lbk][lbn4] = bv;
        }
        __syncthreads();
        #pragma unroll
        for (int k = 0; k < 8; k++) {
            float a[8], b[8];
            *(float4*)&a[0] = *(const float4*)&As[k][tr * 8];
            *(float4*)&a[4] = *(const float4*)&As[k][tr * 8 + 4];
            *(float4*)&b[0] = *(const float4*)&Bs[k][tc * 8];
            *(float4*)&b[4] = *(const float4*)&Bs[k][tc * 8 + 4];
            #pragma unroll
            for (int i = 0; i < 8; i++)
                #pragma unroll
                for (int j = 0; j < 8; j++)
                    acc[i][j] = fmaf(a[i], b[j], acc[i][j]);
        }
        __syncthreads();
    }

    if (SCATTER) {
        // C is [bh][n][qk]: global row r -> (b,n); global col c -> (h,q)
        #pragma unroll
        for (int i = 0; i < 8; i++) {
            int r  = m0 + tr * 8 + i;
            int b_ = r >> 10, n_ = r & 1023;
            #pragma unroll
            for (int j4 = 0; j4 < 8; j4 += 4) {
                int cfull = n0 + tc * 8 + j4;
                int h_ = cfull >> 6, q_ = cfull & 63;
                float4 v = make_float4(acc[i][j4] * alpha, acc[i][j4 + 1] * alpha,
                                       acc[i][j4 + 2] * alpha, acc[i][j4 + 3] * alpha);
                *(float4*)&C[(((size_t)(b_ * Hh + h_)) * Nn + n_) * QKd + q_] = v;
            }
        }
    } else if (RELU) {
        float hs = 0.f;
        #pragma unroll
        for (int i = 0; i < 8; i++) {
            size_t off = (size_t)(m0 + tr * 8 + i) * Ncols + n0 + tc * 8;
            #pragma unroll
            for (int j4 = 0; j4 < 8; j4 += 4) {
                float4 v;
                v.x = fmaxf(acc[i][j4 + 0], 0.f);
                v.y = fmaxf(acc[i][j4 + 1], 0.f);
                v.z = fmaxf(acc[i][j4 + 2], 0.f);
                v.w = fmaxf(acc[i][j4 + 3], 0.f);
                *(float4*)&C[off + j4] = v;
                hs += v.x * v.x + v.y * v.y + v.z * v.z + v.w * v.w;
            }
        }
        __shared__ double sred[256];
        sred[t] = (double)hs;
        __syncthreads();
        for (int o = 128; o > 0; o >>= 1) { if (t < o) sred[t] += sred[t + o]; __syncthreads(); }
        if (t == 0) part[blockIdx.y * gridDim.x + blockIdx.x] = sred[0];
    } else {
        #pragma unroll
        for (int i = 0; i < 8; i++) {
            size_t off = (size_t)(m0 + tr * 8 + i) * Ncols + n0 + tc * 8;
            #pragma unroll
            for (int j4 = 0; j4 < 8; j4 += 4) {
                float4 v = make_float4(acc[i][j4] * alpha, acc[i][j4 + 1] * alpha,
                                       acc[i][j4 + 2] * alpha, acc[i][j4 + 3] * alpha);
                if (accFlag) {
                    float4 o4 = *(const float4*)&C[off + j4];
                    v.x += o4.x; v.y += o4.y; v.z += o4.z; v.w += o4.w;
                }
                *(float4*)&C[off + j4] = v;
            }
        }
    }
}

// ============================================================================
// Attention pass 1: S[bh][n][m] = BETA * <Q_bh[n], K_bh[m]>, + streaming rowmax.
// grid (N/64, BH), 256 threads, 4x4 micro-tile over a 64x64 output tile.
// ============================================================================
__global__ void __launch_bounds__(256) att_s_rowmax(
    const float* __restrict__ Qg, const float* __restrict__ Kg,
    float* __restrict__ S, float* __restrict__ rowmax)
{
    const int bh = blockIdx.y;
    const int n0 = blockIdx.x * 64;
    const float* Q = Qg + (size_t)bh * Nn * QKd;
    const float* K = Kg + (size_t)bh * Nn * QKd;
    float* Srow = S + ((size_t)bh * Nn + n0) * Nn;

    __shared__ float Qs[64][68];
    __shared__ float Kst[64][68];   // [q][m]
    __shared__ float red[64][17];
    __shared__ float rmaxS[64];

    const int t = threadIdx.x;
    const int ty = t >> 4, tx = t & 15;

    #pragma unroll
    for (int i = 0; i < 16; i++) {
        int l = i * 256 + t; int r = l >> 6, c = l & 63;
        Qs[r][c] = Q[(size_t)(n0 + r) * QKd + c];
    }
    if (t < 64) rmaxS[t] = -CUDART_INF_F;
    __syncthreads();

    for (int kt = 0; kt < 16; kt++) {
        #pragma unroll
        for (int i = 0; i < 16; i++) {
            int l = i * 256 + t; int m = l >> 6, q = l & 63;
            Kst[q][m] = K[(size_t)(kt * 64 + m) * QKd + q];
        }
        __syncthreads();

        float c_[4][4] = {};
        #pragma unroll
        for (int q = 0; q < 64; q += 4) {
            float a[4][4], b[4][4];
            #pragma unroll
            for (int i = 0; i < 4; i++)
                *(float4*)&a[i][0] = *(const float4*)&Qs[ty * 4 + i][q];
            #pragma unroll
            for (int r = 0; r < 4; r++)
                *(float4*)&b[r][0] = *(const float4*)&Kst[q + r][tx * 4];
            #pragma unroll
            for (int i = 0; i < 4; i++)
                #pragma unroll
                for (int j = 0; j < 4; j++)
                    c_[i][j] += a[i][0] * b[0][j] + a[i][1] * b[1][j]
                              + a[i][2] * b[2][j] + a[i][3] * b[3][j];
        }

        #pragma unroll
        for (int i = 0; i < 4; i++) {
            float4 v = make_float4(c_[i][0] * BETA, c_[i][1] * BETA,
                                   c_[i][2] * BETA, c_[i][3] * BETA);
            *(float4*)&Srow[(size_t)(ty * 4 + i) * Nn + kt * 64 + tx * 4] = v;
            red[ty * 4 + i][tx] = fmaxf(fmaxf(v.x, v.y), fmaxf(v.z, v.w));
        }
        __syncthreads();
        if (t < 64) {
            float m = rmaxS[t];
            #pragma unroll
            for (int j = 0; j < 16; j++) m = fmaxf(m, red[t][j]);
            rmaxS[t] = m;
        }
        __syncthreads();
    }
    if (t < 64) rowmax[bh * Nn + n0 + t] = rmaxS[t];
}

// ============================================================================
// Convert: S <- exp(S - rowmax[n]) in place; inv[n] = 1/rowsum;
// lse partials (deterministic). grid (N/16, BH), 256 threads = 16 rows x 16 lanes.
// ============================================================================
__global__ void __launch_bounds__(256) att_convert(
    float* __restrict__ S, const float* __restrict__ rowmax,
    float* __restrict__ inv, double* __restrict__ lse_part)
{
    const int bh = blockIdx.y;
    const int r0 = blockIdx.x * 16;
    const int t = threadIdx.x;
    const int rloc = t >> 4, lane = t & 15;
    const int row = r0 + rloc;
    const float rm = rowmax[bh * Nn + row];
    float* Sr = S + ((size_t)bh * Nn + row) * Nn;

    float sum = 0.f;
    #pragma unroll 4
    for (int i = 0; i < 64; i++) {
        int c = i * 16 + lane;
        float e = __expf(Sr[c] - rm);
        Sr[c] = e;
        sum += e;
    }
    #pragma unroll
    for (int o = 8; o > 0; o >>= 1) sum += __shfl_xor_sync(0xffffffffu, sum, o);

    __shared__ double part[16];
    if (lane == 0) {
        inv[bh * Nn + row] = 1.f / sum;
        part[rloc] = (double)rm + (double)logf(sum);
    }
    __syncthreads();
    if (t == 0) {
        double s = 0.0;
        #pragma unroll
        for (int i = 0; i < 16; i++) s += part[i];
        lse_part[bh * (Nn / 16) + blockIdx.x] = s;
    }
}

// ============================================================================
// dQ[bh][n][q] = -inv[n] * sum_m P'[n][m] * K[bh][m][q]
// grid (N/64, BH)
// ============================================================================
__global__ void __launch_bounds__(256) att_dq(
    const float* __restrict__ P, const float* __restrict__ Kg,
    const float* __restrict__ inv, float* __restrict__ dQ)
{
    const int bh = blockIdx.y;
    const int n0 = blockIdx.x * 64;
    const float* Pg = P + ((size_t)bh * Nn + n0) * Nn;
    const float* K = Kg + (size_t)bh * Nn * QKd;
    __shared__ float Ps[64][68];
    __shared__ float Ks[64][64];
    const int t = threadIdx.x, ty = t >> 4, tx = t & 15;
    float acc[4][4] = {};

    for (int kt = 0; kt < 16; kt++) {
        #pragma unroll
        for (int i = 0; i < 16; i++) {
            int l = i * 256 + t; int r = l >> 6, c = l & 63;
            Ps[r][c] = Pg[(size_t)r * Nn + kt * 64 + c];
            Ks[r][c] = K[(size_t)(kt * 64 + r) * QKd + c];
        }
        __syncthreads();
        #pragma unroll
        for (int m = 0; m < 64; m += 4) {
            float a[4][4], b[4][4];
            #pragma unroll
            for (int i = 0; i < 4; i++)
                *(float4*)&a[i][0] = *(const float4*)&Ps[ty * 4 + i][m];
            #pragma unroll
            for (int r = 0; r < 4; r++)
                *(float4*)&b[r][0] = *(const float4*)&Ks[m + r][tx * 4];
            #pragma unroll
            for (int i = 0; i < 4; i++)
                #pragma unroll
                for (int j = 0; j < 4; j++)
                    acc[i][j] += a[i][0] * b[0][j] + a[i][1] * b[1][j]
                               + a[i][2] * b[2][j] + a[i][3] * b[3][j];
        }
        __syncthreads();
    }
    #pragma unroll
    for (int i = 0; i < 4; i++) {
        int n = n0 + ty * 4 + i;
        float s = -inv[bh * Nn + n];
        float4 v = make_float4(acc[i][0] * s, acc[i][1] * s, acc[i][2] * s, acc[i][3] * s);
        *(float4*)&dQ[((size_t)bh * Nn + n) * QKd + tx * 4] = v;
    }
}

// ============================================================================
// dK[bh][m][q] = -sum_n (P'[n][m] * inv[n]) * Q[bh][n][q]
// grid (N/64, BH)
// ============================================================================
__global__ void __launch_bounds__(256) att_dk(
    const float* __restrict__ P, const float* __restrict__ Qg,
    const float* __restrict__ inv, float* __restrict__ dK)
{
    const int bh = blockIdx.y;
    const int m0 = blockIdx.x * 64;
    const float* Q = Qg + (size_t)bh * Nn * QKd;
    __shared__ float Ps[64][68];   // [n][m], scaled by inv[n]
    __shared__ float Qs[64][64];
    __shared__ float invs[64];
    const int t = threadIdx.x, ty = t >> 4, tx = t & 15;
    float acc[4][4] = {};

    for (int nt = 0; nt < 16; nt++) {
        if (t < 64) invs[t] = inv[bh * Nn + nt * 64 + t];
        __syncthreads();
        #pragma unroll
        for (int i = 0; i < 16; i++) {
            int l = i * 256 + t; int r = l >> 6, c = l & 63;
            Ps[r][c] = P[((size_t)bh * Nn + nt * 64 + r) * Nn + m0 + c] * invs[r];
            Qs[r][c] = Q[(size_t)(nt * 64 + r) * QKd + c];
        }
        __syncthreads();
        #pragma unroll
        for (int n = 0; n < 64; n += 4) {
            float a[4][4], b[4][4];
            #pragma unroll
            for (int r = 0; r < 4; r++) {
                *(float4*)&a[r][0] = *(const float4*)&Ps[n + r][ty * 4];
                *(float4*)&b[r][0] = *(const float4*)&Qs[n + r][tx * 4];
            }
            #pragma unroll
            for (int i = 0; i < 4; i++)
                #pragma unroll
                for (int j = 0; j < 4; j++)
                    acc[i][j] += a[0][i] * b[0][j] + a[1][i] * b[1][j]
                               + a[2][i] * b[2][j] + a[3][i] * b[3][j];
        }
        __syncthreads();
    }
    #pragma unroll
    for (int i = 0; i < 4; i++) {
        int m = m0 + ty * 4 + i;
        float4 v = make_float4(-acc[i][0], -acc[i][1], -acc[i][2], -acc[i][3]);
        *(float4*)&dK[((size_t)bh * Nn + m) * QKd + tx * 4] = v;
    }
}

// ============================================================================
// Repack dQ/dK from [bh][n][qk] to [b*n][h*qk] for the back-projection GEMMs.
// ============================================================================
__global__ void __launch_bounds__(256) repack(
    const float* __restrict__ dQb, const float* __restrict__ dKb,
    float* __restrict__ dQm, float* __restrict__ dKm)
{
    int idx = blockIdx.x * 256 + threadIdx.x;   // over BNr*HQ = 4,194,304
    int q = idx & 63;
    int h = (idx >> 6) & 15;
    int n = (idx >> 10) & 1023;
    int b = idx >> 20;
    size_t src = (((size_t)(b * Hh + h) * Nn) + n) * QKd + q;
    dQm[idx] = dQb[src];
    dKm[idx] = dKb[src];
}

// ============================================================================
// Final energy: E = -(1/BETA) * sum(lse) - 0.5 * sum(h^2). Deterministic.
// ============================================================================
__global__ void energy_final(const double* __restrict__ lse_part,
                             const double* __restrict__ h2_part,
                             float* __restrict__ out)
{
    __shared__ double sm[256];
    int t = threadIdx.x;
    double s = 0.0;
    for (int i = t; i < BH * (Nn / 16); i += 256) s += lse_part[i];
    double s2 = 0.0;
    for (int i = t; i < (BNr / 128) * (HIDd / 128); i += 256) s2 += h2_part[i];
    sm[t] = -8.0 * s - 0.5 * s2;
    __syncthreads();
    for (int o = 128; o > 0; o >>= 1) { if (t < o) sm[t] += sm[t + o]; __syncthreads(); }
    if (t == 0) out[(size_t)BNr * Dd] = (float)sm[0];
}

// ============================================================================
// Host launcher
// ============================================================================
extern "C" void kernel_launch(void* const* d_in, const int* in_sizes, int n_in,
                              void* d_out, int out_size)
{
    const float* x    = (const float*)d_in[0];   // [B,N,D]
    const float* Wq   = (const float*)d_in[1];   // [H,QK,D]
    const float* Wk   = (const float*)d_in[2];   // [H,QK,D]
    const float* Whop = (const float*)d_in[3];   // [D,HID]
    float* out = (float*)d_out;                  // grad [B,N,D] then energy scalar

    float *pQ, *pK, *pdQ, *pdK, *pdQm, *pdKm, *pS, *pRM, *pINV, *pHb;
    double *pLse, *pH2;
    cudaGetSymbolAddress((void**)&pQ,   g_Q);
    cudaGetSymbolAddress((void**)&pK,   g_K);
    cudaGetSymbolAddress((void**)&pdQ,  g_dQ);
    cudaGetSymbolAddress((void**)&pdK,  g_dK);
    cudaGetSymbolAddress((void**)&pdQm, g_dQm);
    cudaGetSymbolAddress((void**)&pdKm, g_dKm);
    cudaGetSymbolAddress((void**)&pS,   g_S);
    cudaGetSymbolAddress((void**)&pRM,  g_rowmax);
    cudaGetSymbolAddress((void**)&pINV, g_inv);
    cudaGetSymbolAddress((void**)&pHb,  g_Hb);
    cudaGetSymbolAddress((void**)&pLse, g_lse_part);
    cudaGetSymbolAddress((void**)&pH2,  g_h2_part);

    dim3 blk(256);

    // 1-2. Q = X Wq^T, K = X Wk^T  (scatter to [bh][n][qk])
    sgemm_k<1, 1, 0><<<dim3(HQ / 128, BNr / 128), blk>>>(x, Wq, pQ, BNr, HQ, Dd, 1.f, 0, nullptr);
    sgemm_k<1, 1, 0><<<dim3(HQ / 128, BNr / 128), blk>>>(x, Wk, pK, BNr, HQ, Dd, 1.f, 0, nullptr);

    // 3. scores + row max
    att_s_rowmax<<<dim3(Nn / 64, BH), blk>>>(pQ, pK, pS, pRM);

    // 4. exp in place, 1/rowsum, lse partials
    att_convert<<<dim3(Nn / 16, BH), blk>>>(pS, pRM, pINV, pLse);

    // 5-6. dQ, dK
    att_dq<<<dim3(Nn / 64, BH), blk>>>(pS, pK, pINV, pdQ);
    att_dk<<<dim3(Nn / 64, BH), blk>>>(pS, pQ, pINV, pdK);

    // 7. repack to [b*n][h*qk]
    repack<<<(BNr * HQ) / 256, blk>>>(pdQ, pdK, pdQm, pdKm);

    // 8-9. grad = dQ @ Wq + dK @ Wk
    sgemm_k<0, 0, 0><<<dim3(Dd / 128, BNr / 128), blk>>>(pdQm, Wq, out, BNr, Dd, HQ, 1.f, 0, nullptr);
    sgemm_k<0, 0, 0><<<dim3(Dd / 128, BNr / 128), blk>>>(pdKm, Wk, out, BNr, Dd, HQ, 1.f, 1, nullptr);

    // 10. Hb = relu(X @ W_hop), accumulate sum(h^2) partials
    sgemm_k<0, 0, 1><<<dim3(HIDd / 128, BNr / 128), blk>>>(x, Whop, pHb, BNr, HIDd, Dd, 1.f, 0, pH2);

    // 11. grad -= Hb @ W_hop^T
    sgemm_k<1, 0, 0><<<dim3(Dd / 128, BNr / 128), blk>>>(pHb, Whop, out, BNr, Dd, HIDd, -1.f, 1, nullptr);

    // 12. energy scalar
    if (out_size > BNr * Dd)
        energy_final<<<1, 256>>>(pLse, pH2, out);
}

// round 6
// speedup vs baseline: 1.0101x; 1.0101x over previous
#include <cuda_runtime.h>
#include <math_constants.h>

#define Bsz 4
#define Nn 1024
#define Dd 1024
#define Hh 16
#define QKd 64
#define HIDd 4096
#define BH 64           // B*H
#define BNr 4096        // B*N
#define HQ 1024         // H*QK
#define BETA 0.125f

typedef unsigned long long u64;

// ---- packed fp32x2 helpers (Blackwell FFMA2 — only reachable via PTX) ----
__device__ __forceinline__ u64 pack2(float lo, float hi) {
    u64 r; asm("mov.b64 %0, {%1, %2};" : "=l"(r) : "f"(lo), "f"(hi)); return r;
}
__device__ __forceinline__ void fma2(u64& d, u64 a, u64 b) {
    asm("fma.rn.f32x2 %0, %1, %2, %0;" : "+l"(d) : "l"(a), "l"(b));
}
__device__ __forceinline__ float2 unpack2(u64 v) {
    float2 f; asm("mov.b64 {%0, %1}, %2;" : "=f"(f.x), "=f"(f.y) : "l"(v)); return f;
}

// -------- device scratch (static allocation; no cudaMalloc anywhere) --------
__device__ float  g_Q  [(size_t)BH * Nn * QKd];   // [bh][n][qk]
__device__ float  g_K  [(size_t)BH * Nn * QKd];
__device__ float  g_dQ [(size_t)BH * Nn * QKd];
__device__ float  g_dK [(size_t)BH * Nn * QKd];
__device__ float  g_dQm[(size_t)BNr * HQ];        // [b*n][h*qk]
__device__ float  g_dKm[(size_t)BNr * HQ];
__device__ float  g_S  [(size_t)BH * Nn * Nn];    // scores, then exp'ed probs (256MB)
__device__ float  g_rowmax[BH * Nn];
__device__ float  g_inv  [BH * Nn];
__device__ float  g_Hb [(size_t)BNr * HIDd];      // relu(x @ W_hop)
__device__ double g_lse_part[BH * (Nn / 16)];     // 4096
__device__ double g_h2_part [(BNr / 128) * (HIDd / 128)]; // 1024

// ============================================================================
// Generic 128x128x8 SGEMM, 256 threads, 8x8 micro-tile, packed f32x2 FMA.
//   TB=1:     C[m,n] = sum_k A[m,k] * B[n,k]   (B row-major [Ncols, Kd])
//   TB=0:     C[m,n] = sum_k A[m,k] * B[k,n]   (B row-major [Kd, Ncols])
//   SCATTER:  write C into [bh][n][qk] layout (forward Q/K projections)
//   RELU:     v = max(v,0); store; accumulate sum(v^2) per block into part[]
//   else:     C = alpha*acc  or  C += alpha*acc  (accFlag)
// ============================================================================
template<int TB, int SCATTER, int RELU>
__global__ void __launch_bounds__(256) sgemm_k(
    const float* __restrict__ A, const float* __restrict__ B, float* __restrict__ C,
    int M, int Ncols, int Kd, float alpha, int accFlag, double* __restrict__ part)
{
    __shared__ float As[8][132];
    __shared__ float Bs[8][132];
    const int t  = threadIdx.x;
    const int m0 = blockIdx.y * 128;
    const int n0 = blockIdx.x * 128;
    const int tr = t >> 4;
    const int tc = t & 15;
    const int lrow = t >> 1;          // 0..127
    const int lk4  = (t & 1) * 4;     // 0 or 4
    const int lbk  = t >> 5;          // 0..7
    const int lbn4 = (t & 31) * 4;    // 0..124

    u64 acc[8][4];
    #pragma unroll
    for (int i = 0; i < 8; i++)
        #pragma unroll
        for (int j = 0; j < 4; j++) acc[i][j] = 0ull;

    const float* Aptr = A + (size_t)(m0 + lrow) * Kd + lk4;
    const float* Bptr = TB ? (B + (size_t)(n0 + lrow) * Kd + lk4)
                           : (B + (size_t)lbk * Ncols + n0 + lbn4);

    for (int kt = 0; kt < Kd; kt += 8) {
        float4 av = *(const float4*)(Aptr + kt);
        As[lk4 + 0][lrow] = av.x; As[lk4 + 1][lrow] = av.y;
        As[lk4 + 2][lrow] = av.z; As[lk4 + 3][lrow] = av.w;
        if (TB) {
            float4 bv = *(const float4*)(Bptr + kt);
            Bs[lk4 + 0][lrow] = bv.x; Bs[lk4 + 1][lrow] = bv.y;
            Bs[lk4 + 2][lrow] = bv.z; Bs[lk4 + 3][lrow] = bv.w;
        } else {
            float4 bv = *(const float4*)(Bptr + (size_t)kt * Ncols);
            *(float4*)&Bs[lbk][lbn4] = bv;
        }
        __syncthreads();
        #pragma unroll
        for (int k = 0; k < 8; k++) {
            float a[8];
            *(float4*)&a[0] = *(const float4*)&As[k][tr * 8];
            *(float4*)&a[4] = *(const float4*)&As[k][tr * 8 + 4];
            u64 b2[4];
            #pragma unroll
            for (int j = 0; j < 4; j++)
                b2[j] = *(const u64*)&Bs[k][tc * 8 + j * 2];
            #pragma unroll
            for (int i = 0; i < 8; i++) {
                u64 a2 = pack2(a[i], a[i]);
                #pragma unroll
                for (int j = 0; j < 4; j++)
                    fma2(acc[i][j], a2, b2[j]);
            }
        }
        __syncthreads();
    }

    // unpack accumulators
    float c[8][8];
    #pragma unroll
    for (int i = 0; i < 8; i++)
        #pragma unroll
        for (int j = 0; j < 4; j++) {
            float2 p = unpack2(acc[i][j]);
            c[i][2 * j] = p.x; c[i][2 * j + 1] = p.y;
        }

    if (SCATTER) {
        // C is [bh][n][qk]: global row r -> (b,n); global col cc -> (h,q)
        #pragma unroll
        for (int i = 0; i < 8; i++) {
            int r  = m0 + tr * 8 + i;
            int b_ = r >> 10, n_ = r & 1023;
            #pragma unroll
            for (int j4 = 0; j4 < 8; j4 += 4) {
                int cfull = n0 + tc * 8 + j4;
                int h_ = cfull >> 6, q_ = cfull & 63;
                float4 v = make_float4(c[i][j4] * alpha, c[i][j4 + 1] * alpha,
                                       c[i][j4 + 2] * alpha, c[i][j4 + 3] * alpha);
                *(float4*)&C[(((size_t)(b_ * Hh + h_)) * Nn + n_) * QKd + q_] = v;
            }
        }
    } else if (RELU) {
        float hs = 0.f;
        #pragma unroll
        for (int i = 0; i < 8; i++) {
            size_t off = (size_t)(m0 + tr * 8 + i) * Ncols + n0 + tc * 8;
            #pragma unroll
            for (int j4 = 0; j4 < 8; j4 += 4) {
                float4 v;
                v.x = fmaxf(c[i][j4 + 0], 0.f);
                v.y = fmaxf(c[i][j4 + 1], 0.f);
                v.z = fmaxf(c[i][j4 + 2], 0.f);
                v.w = fmaxf(c[i][j4 + 3], 0.f);
                *(float4*)&C[off + j4] = v;
                hs += v.x * v.x + v.y * v.y + v.z * v.z + v.w * v.w;
            }
        }
        __shared__ double sred[256];
        sred[t] = (double)hs;
        __syncthreads();
        for (int o = 128; o > 0; o >>= 1) { if (t < o) sred[t] += sred[t + o]; __syncthreads(); }
        if (t == 0) part[blockIdx.y * gridDim.x + blockIdx.x] = sred[0];
    } else {
        #pragma unroll
        for (int i = 0; i < 8; i++) {
            size_t off = (size_t)(m0 + tr * 8 + i) * Ncols + n0 + tc * 8;
            #pragma unroll
            for (int j4 = 0; j4 < 8; j4 += 4) {
                float4 v = make_float4(c[i][j4] * alpha, c[i][j4 + 1] * alpha,
                                       c[i][j4 + 2] * alpha, c[i][j4 + 3] * alpha);
                if (accFlag) {
                    float4 o4 = *(const float4*)&C[off + j4];
                    v.x += o4.x; v.y += o4.y; v.z += o4.z; v.w += o4.w;
                }
                *(float4*)&C[off + j4] = v;
            }
        }
    }
}

// ============================================================================
// Attention pass 1: S[bh][n][m] = BETA * <Q_bh[n], K_bh[m]>, + streaming rowmax.
// grid (N/64, BH), 256 threads, 4x4 micro-tile, packed FMA.
// ============================================================================
__global__ void __launch_bounds__(256) att_s_rowmax(
    const float* __restrict__ Qg, const float* __restrict__ Kg,
    float* __restrict__ S, float* __restrict__ rowmax)
{
    const int bh = blockIdx.y;
    const int n0 = blockIdx.x * 64;
    const float* Q = Qg + (size_t)bh * Nn * QKd;
    const float* K = Kg + (size_t)bh * Nn * QKd;
    float* Srow = S + ((size_t)bh * Nn + n0) * Nn;

    __shared__ float Qs[64][68];
    __shared__ float Kst[64][68];   // [q][m]
    __shared__ float red[64][17];
    __shared__ float rmaxS[64];

    const int t = threadIdx.x;
    const int ty = t >> 4, tx = t & 15;

    #pragma unroll
    for (int i = 0; i < 16; i++) {
        int l = i * 256 + t; int r = l >> 6, cc = l & 63;
        Qs[r][cc] = Q[(size_t)(n0 + r) * QKd + cc];
    }
    if (t < 64) rmaxS[t] = -CUDART_INF_F;
    __syncthreads();

    for (int kt = 0; kt < 16; kt++) {
        #pragma unroll
        for (int i = 0; i < 16; i++) {
            int l = i * 256 + t; int m = l >> 6, q = l & 63;
            Kst[q][m] = K[(size_t)(kt * 64 + m) * QKd + q];
        }
        __syncthreads();

        u64 acc[4][2] = {{0ull,0ull},{0ull,0ull},{0ull,0ull},{0ull,0ull}};
        #pragma unroll
        for (int q = 0; q < 64; q += 4) {
            float a_[4][4];
            #pragma unroll
            for (int i = 0; i < 4; i++)
                *(float4*)&a_[i][0] = *(const float4*)&Qs[ty * 4 + i][q];
            u64 b2[4][2];
            #pragma unroll
            for (int r = 0; r < 4; r++) {
                b2[r][0] = *(const u64*)&Kst[q + r][tx * 4];
                b2[r][1] = *(const u64*)&Kst[q + r][tx * 4 + 2];
            }
            #pragma unroll
            for (int i = 0; i < 4; i++)
                #pragma unroll
                for (int r = 0; r < 4; r++) {
                    u64 a2 = pack2(a_[i][r], a_[i][r]);
                    fma2(acc[i][0], a2, b2[r][0]);
                    fma2(acc[i][1], a2, b2[r][1]);
                }
        }

        #pragma unroll
        for (int i = 0; i < 4; i++) {
            float2 p0 = unpack2(acc[i][0]);
            float2 p1 = unpack2(acc[i][1]);
            float4 v = make_float4(p0.x * BETA, p0.y * BETA, p1.x * BETA, p1.y * BETA);
            *(float4*)&Srow[(size_t)(ty * 4 + i) * Nn + kt * 64 + tx * 4] = v;
            red[ty * 4 + i][tx] = fmaxf(fmaxf(v.x, v.y), fmaxf(v.z, v.w));
        }
        __syncthreads();
        if (t < 64) {
            float m = rmaxS[t];
            #pragma unroll
            for (int j = 0; j < 16; j++) m = fmaxf(m, red[t][j]);
            rmaxS[t] = m;
        }
        __syncthreads();
    }
    if (t < 64) rowmax[bh * Nn + n0 + t] = rmaxS[t];
}

// ============================================================================
// Convert: S <- exp(S - rowmax[n]) in place; inv[n] = 1/rowsum;
// lse partials (deterministic). grid (N/16, BH), 256 threads = 16 rows x 16 lanes.
// ============================================================================
__global__ void __launch_bounds__(256) att_convert(
    float* __restrict__ S, const float* __restrict__ rowmax,
    float* __restrict__ inv, double* __restrict__ lse_part)
{
    const int bh = blockIdx.y;
    const int r0 = blockIdx.x * 16;
    const int t = threadIdx.x;
    const int rloc = t >> 4, lane = t & 15;
    const int row = r0 + rloc;
    const float rm = rowmax[bh * Nn + row];
    float* Sr = S + ((size_t)bh * Nn + row) * Nn;

    float sum = 0.f;
    #pragma unroll 4
    for (int i = 0; i < 64; i++) {
        int c = i * 16 + lane;
        float e = __expf(Sr[c] - rm);
        Sr[c] = e;
        sum += e;
    }
    #pragma unroll
    for (int o = 8; o > 0; o >>= 1) sum += __shfl_xor_sync(0xffffffffu, sum, o);

    __shared__ double part[16];
    if (lane == 0) {
        inv[bh * Nn + row] = 1.f / sum;
        part[rloc] = (double)rm + (double)logf(sum);
    }
    __syncthreads();
    if (t == 0) {
        double s = 0.0;
        #pragma unroll
        for (int i = 0; i < 16; i++) s += part[i];
        lse_part[bh * (Nn / 16) + blockIdx.x] = s;
    }
}

// ============================================================================
// dQ[bh][n][q] = -inv[n] * sum_m P'[n][m] * K[bh][m][q]   (packed FMA)
// ============================================================================
__global__ void __launch_bounds__(256) att_dq(
    const float* __restrict__ P, const float* __restrict__ Kg,
    const float* __restrict__ inv, float* __restrict__ dQ)
{
    const int bh = blockIdx.y;
    const int n0 = blockIdx.x * 64;
    const float* Pg = P + ((size_t)bh * Nn + n0) * Nn;
    const float* K = Kg + (size_t)bh * Nn * QKd;
    __shared__ float Ps[64][68];
    __shared__ float Ks[64][64];
    const int t = threadIdx.x, ty = t >> 4, tx = t & 15;
    u64 acc[4][2] = {{0ull,0ull},{0ull,0ull},{0ull,0ull},{0ull,0ull}};

    for (int kt = 0; kt < 16; kt++) {
        #pragma unroll
        for (int i = 0; i < 16; i++) {
            int l = i * 256 + t; int r = l >> 6, c = l & 63;
            Ps[r][c] = Pg[(size_t)r * Nn + kt * 64 + c];
            Ks[r][c] = K[(size_t)(kt * 64 + r) * QKd + c];
        }
        __syncthreads();
        #pragma unroll
        for (int m = 0; m < 64; m += 4) {
            float a_[4][4];
            #pragma unroll
            for (int i = 0; i < 4; i++)
                *(float4*)&a_[i][0] = *(const float4*)&Ps[ty * 4 + i][m];
            u64 b2[4][2];
            #pragma unroll
            for (int r = 0; r < 4; r++) {
                b2[r][0] = *(const u64*)&Ks[m + r][tx * 4];
                b2[r][1] = *(const u64*)&Ks[m + r][tx * 4 + 2];
            }
            #pragma unroll
            for (int i = 0; i < 4; i++)
                #pragma unroll
                for (int r = 0; r < 4; r++) {
                    u64 a2 = pack2(a_[i][r], a_[i][r]);
                    fma2(acc[i][0], a2, b2[r][0]);
                    fma2(acc[i][1], a2, b2[r][1]);
                }
        }
        __syncthreads();
    }
    #pragma unroll
    for (int i = 0; i < 4; i++) {
        int n = n0 + ty * 4 + i;
        float s = -inv[bh * Nn + n];
        float2 p0 = unpack2(acc[i][0]);
        float2 p1 = unpack2(acc[i][1]);
        float4 v = make_float4(p0.x * s, p0.y * s, p1.x * s, p1.y * s);
        *(float4*)&dQ[((size_t)bh * Nn + n) * QKd + tx * 4] = v;
    }
}

// ============================================================================
// dK[bh][m][q] = -sum_n (P'[n][m] * inv[n]) * Q[bh][n][q]   (packed FMA)
// ============================================================================
__global__ void __launch_bounds__(256) att_dk(
    const float* __restrict__ P, const float* __restrict__ Qg,
    const float* __restrict__ inv, float* __restrict__ dK)
{
    const int bh = blockIdx.y;
    const int m0 = blockIdx.x * 64;
    const float* Q = Qg + (size_t)bh * Nn * QKd;
    __shared__ float Ps[64][68];   // [n][m], scaled by inv[n]
    __shared__ float Qs[64][64];
    __shared__ float invs[64];
    const int t = threadIdx.x, ty = t >> 4, tx = t & 15;
    u64 acc[4][2] = {{0ull,0ull},{0ull,0ull},{0ull,0ull},{0ull,0ull}};

    for (int nt = 0; nt < 16; nt++) {
        if (t < 64) invs[t] = inv[bh * Nn + nt * 64 + t];
        __syncthreads();
        #pragma unroll
        for (int i = 0; i < 16; i++) {
            int l = i * 256 + t; int r = l >> 6, c = l & 63;
            Ps[r][c] = P[((size_t)bh * Nn + nt * 64 + r) * Nn + m0 + c] * invs[r];
            Qs[r][c] = Q[(size_t)(nt * 64 + r) * QKd + c];
        }
        __syncthreads();
        #pragma unroll
        for (int n = 0; n < 64; n += 4) {
            float a_[4][4];  // a_[r][i] = Ps[n+r][ty*4+i]
            #pragma unroll
            for (int r = 0; r < 4; r++)
                *(float4*)&a_[r][0] = *(const float4*)&Ps[n + r][ty * 4];
            u64 b2[4][2];
            #pragma unroll
            for (int r = 0; r < 4; r++) {
                b2[r][0] = *(const u64*)&Qs[n + r][tx * 4];
                b2[r][1] = *(const u64*)&Qs[n + r][tx * 4 + 2];
            }
            #pragma unroll
            for (int i = 0; i < 4; i++)
                #pragma unroll
                for (int r = 0; r < 4; r++) {
                    u64 a2 = pack2(a_[r][i], a_[r][i]);
                    fma2(acc[i][0], a2, b2[r][0]);
                    fma2(acc[i][1], a2, b2[r][1]);
                }
        }
        __syncthreads();
    }
    #pragma unroll
    for (int i = 0; i < 4; i++) {
        int m = m0 + ty * 4 + i;
        float2 p0 = unpack2(acc[i][0]);
        float2 p1 = unpack2(acc[i][1]);
        float4 v = make_float4(-p0.x, -p0.y, -p1.x, -p1.y);
        *(float4*)&dK[((size_t)bh * Nn + m) * QKd + tx * 4] = v;
    }
}

// ============================================================================
// Repack dQ/dK from [bh][n][qk] to [b*n][h*qk] for the back-projection GEMMs.
// ============================================================================
__global__ void __launch_bounds__(256) repack(
    const float* __restrict__ dQb, const float* __restrict__ dKb,
    float* __restrict__ dQm, float* __restrict__ dKm)
{
    int idx = blockIdx.x * 256 + threadIdx.x;   // over BNr*HQ = 4,194,304
    int q = idx & 63;
    int h = (idx >> 6) & 15;
    int n = (idx >> 10) & 1023;
    int b = idx >> 20;
    size_t src = (((size_t)(b * Hh + h) * Nn) + n) * QKd + q;
    dQm[idx] = dQb[src];
    dKm[idx] = dKb[src];
}

// ============================================================================
// Final energy: E = -(1/BETA) * sum(lse) - 0.5 * sum(h^2). Deterministic.
// ============================================================================
__global__ void energy_final(const double* __restrict__ lse_part,
                             const double* __restrict__ h2_part,
                             float* __restrict__ out)
{
    __shared__ double sm[256];
    int t = threadIdx.x;
    double s = 0.0;
    for (int i = t; i < BH * (Nn / 16); i += 256) s += lse_part[i];
    double s2 = 0.0;
    for (int i = t; i < (BNr / 128) * (HIDd / 128); i += 256) s2 += h2_part[i];
    sm[t] = -8.0 * s - 0.5 * s2;
    __syncthreads();
    for (int o = 128; o > 0; o >>= 1) { if (t < o) sm[t] += sm[t + o]; __syncthreads(); }
    if (t == 0) out[(size_t)BNr * Dd] = (float)sm[0];
}

// ============================================================================
// Host launcher
// ============================================================================
extern "C" void kernel_launch(void* const* d_in, const int* in_sizes, int n_in,
                              void* d_out, int out_size)
{
    const float* x    = (const float*)d_in[0];   // [B,N,D]
    const float* Wq   = (const float*)d_in[1];   // [H,QK,D]
    const float* Wk   = (const float*)d_in[2];   // [H,QK,D]
    const float* Whop = (const float*)d_in[3];   // [D,HID]
    float* out = (float*)d_out;                  // grad [B,N,D] then energy scalar

    float *pQ, *pK, *pdQ, *pdK, *pdQm, *pdKm, *pS, *pRM, *pINV, *pHb;
    double *pLse, *pH2;
    cudaGetSymbolAddress((void**)&pQ,   g_Q);
    cudaGetSymbolAddress((void**)&pK,   g_K);
    cudaGetSymbolAddress((void**)&pdQ,  g_dQ);
    cudaGetSymbolAddress((void**)&pdK,  g_dK);
    cudaGetSymbolAddress((void**)&pdQm, g_dQm);
    cudaGetSymbolAddress((void**)&pdKm, g_dKm);
    cudaGetSymbolAddress((void**)&pS,   g_S);
    cudaGetSymbolAddress((void**)&pRM,  g_rowmax);
    cudaGetSymbolAddress((void**)&pINV, g_inv);
    cudaGetSymbolAddress((void**)&pHb,  g_Hb);
    cudaGetSymbolAddress((void**)&pLse, g_lse_part);
    cudaGetSymbolAddress((void**)&pH2,  g_h2_part);

    dim3 blk(256);

    // 1-2. Q = X Wq^T, K = X Wk^T  (scatter to [bh][n][qk])
    sgemm_k<1, 1, 0><<<dim3(HQ / 128, BNr / 128), blk>>>(x, Wq, pQ, BNr, HQ, Dd, 1.f, 0, nullptr);
    sgemm_k<1, 1, 0><<<dim3(HQ / 128, BNr / 128), blk>>>(x, Wk, pK, BNr, HQ, Dd, 1.f, 0, nullptr);

    // 3. scores + row max
    att_s_rowmax<<<dim3(Nn / 64, BH), blk>>>(pQ, pK, pS, pRM);

    // 4. exp in place, 1/rowsum, lse partials
    att_convert<<<dim3(Nn / 16, BH), blk>>>(pS, pRM, pINV, pLse);

    // 5-6. dQ, dK
    att_dq<<<dim3(Nn / 64, BH), blk>>>(pS, pK, pINV, pdQ);
    att_dk<<<dim3(Nn / 64, BH), blk>>>(pS, pQ, pINV, pdK);

    // 7. repack to [b*n][h*qk]
    repack<<<(BNr * HQ) / 256, blk>>>(pdQ, pdK, pdQm, pdKm);

    // 8-9. grad = dQ @ Wq + dK @ Wk
    sgemm_k<0, 0, 0><<<dim3(Dd / 128, BNr / 128), blk>>>(pdQm, Wq, out, BNr, Dd, HQ, 1.f, 0, nullptr);
    sgemm_k<0, 0, 0><<<dim3(Dd / 128, BNr / 128), blk>>>(pdKm, Wk, out, BNr, Dd, HQ, 1.f, 1, nullptr);

    // 10. Hb = relu(X @ W_hop), accumulate sum(h^2) partials
    sgemm_k<0, 0, 1><<<dim3(HIDd / 128, BNr / 128), blk>>>(x, Whop, pHb, BNr, HIDd, Dd, 1.f, 0, pH2);

    // 11. grad -= Hb @ W_hop^T
    sgemm_k<1, 0, 0><<<dim3(Dd / 128, BNr / 128), blk>>>(pHb, Whop, out, BNr, Dd, HIDd, -1.f, 1, nullptr);

    // 12. energy scalar
    if (out_size > BNr * Dd)
        energy_final<<<1, 256>>>(pLse, pH2, out);
}

// round 8
// speedup vs baseline: 1.7475x; 1.7301x over previous
#include <cuda_runtime.h>
#include <cuda_bf16.h>
#include <math_constants.h>
#include <cstdint>

#define Bsz 4
#define Nn 1024
#define Dd 1024
#define Hh 16
#define QKd 64
#define HIDd 4096
#define BH 64           // B*H
#define BNr 4096        // B*N
#define HQ 1024         // H*QK
#define BETA 0.125f

typedef unsigned long long u64;
typedef __nv_bfloat16 bf16;

__device__ __forceinline__ uint32_t smem_u32(const void* p) {
    uint32_t a;
    asm("{ .reg .u64 t; cvta.to.shared.u64 t, %1; cvt.u32.u64 %0, t; }" : "=r"(a) : "l"(p));
    return a;
}
__device__ __forceinline__ void split2(float v, bf16& h, bf16& l) {
    h = __float2bfloat16(v);
    l = __float2bfloat16(v - __bfloat162float(h));
}

// -------- device scratch (static allocation; no cudaMalloc anywhere) --------
__device__ float  g_Q  [(size_t)BH * Nn * QKd];   // [bh][n][qk]
__device__ float  g_K  [(size_t)BH * Nn * QKd];
__device__ float  g_dQ [(size_t)BH * Nn * QKd];
__device__ float  g_dK [(size_t)BH * Nn * QKd];
__device__ float  g_S  [(size_t)BH * Nn * Nn];    // scores, then exp'ed probs (256MB)
__device__ float  g_rowmax[BH * Nn];
__device__ float  g_inv  [BH * Nn];
__device__ double g_lse_part[BH * (Nn / 16)];
__device__ double g_h2_part [(BNr / 128) * (HIDd / 128)];

// bf16 split planes
__device__ bf16 g_x1 [(size_t)BNr * Dd],   g_x2 [(size_t)BNr * Dd];
__device__ bf16 g_wq1[(size_t)HQ * Dd],    g_wq2[(size_t)HQ * Dd];
__device__ bf16 g_wk1[(size_t)HQ * Dd],    g_wk2[(size_t)HQ * Dd];
__device__ bf16 g_wqt1[(size_t)Dd * HQ],   g_wqt2[(size_t)Dd * HQ];
__device__ bf16 g_wkt1[(size_t)Dd * HQ],   g_wkt2[(size_t)Dd * HQ];
__device__ bf16 g_wh1[(size_t)Dd * HIDd],  g_wh2[(size_t)Dd * HIDd];
__device__ bf16 g_wht1[(size_t)HIDd * Dd], g_wht2[(size_t)HIDd * Dd];
__device__ bf16 g_hb1[(size_t)BNr * HIDd], g_hb2[(size_t)BNr * HIDd];
__device__ bf16 g_dqm1[(size_t)BNr * HQ],  g_dqm2[(size_t)BNr * HQ];
__device__ bf16 g_dkm1[(size_t)BNr * HQ],  g_dkm2[(size_t)BNr * HQ];

// ============================================================================
// Split kernels: fp32 -> (hi, lo) bf16 planes
// ============================================================================
__global__ void __launch_bounds__(256) split_plain(
    const float* __restrict__ in, bf16* __restrict__ o1, bf16* __restrict__ o2)
{
    size_t i = (size_t)blockIdx.x * 256 + threadIdx.x;
    bf16 h, l; split2(in[i], h, l);
    o1[i] = h; o2[i] = l;
}
__global__ void __launch_bounds__(256) split_trans(
    const float* __restrict__ in, bf16* __restrict__ o1, bf16* __restrict__ o2,
    int R, int Ccols)
{
    size_t idx = (size_t)blockIdx.x * 256 + threadIdx.x;
    int r = (int)(idx % R);
    int c = (int)(idx / R);
    bf16 h, l; split2(in[(size_t)r * Ccols + c], h, l);
    o1[idx] = h; o2[idx] = l;
}

// ============================================================================
// HMMA bf16x2 GEMM: C[m,n] = alpha * sum_k A[m,k]*B[n,k]  (3-sweep hi/lo split)
// mma.sync m16n8k16, 128x128 block tile, 8 warps x (64x32), cp.async 2-stage.
// Smem tile rows padded to 144B (72 bf16): ldmatrix phase conflict-free.
//   EPI=0: C (+)= alpha*D    EPI=1: scatter to [bh][n][qk]
//   EPI=2: relu; bf16-split to O1/O2; sum(v^2) partials to part
// ============================================================================
#define TILE_B 36864            // bytes per stage (A 18432 + B 18432)
#define ROWSTR 144              // bytes per padded smem row (72 bf16)
#define TG_SMEM (2 * TILE_B)

template<int EPI>
__global__ void __launch_bounds__(256) tgemm(
    const bf16* __restrict__ A1, const bf16* __restrict__ A2,
    const bf16* __restrict__ B1, const bf16* __restrict__ B2,
    float* __restrict__ C, int Ncols, int Kglob, float alpha, int accFlag,
    bf16* __restrict__ O1, bf16* __restrict__ O2, double* __restrict__ part)
{
    extern __shared__ char dsm[];
    __shared__ double sred[256];
    const uint32_t sbase = smem_u32(dsm);

    const int t = threadIdx.x;
    const int wid = t >> 5, lane = t & 31;
    const int m0 = blockIdx.y * 128, n0 = blockIdx.x * 128;
    const int wm = wid >> 2, wn = wid & 3;    // 2 x 4 warp grid

    const int KC = Kglob >> 6;                 // 64-wide bf16 k-chunks
    const int TOT = 3 * KC;                    // 3 split sweeps

    float acc[4][4][4];
    #pragma unroll
    for (int i = 0; i < 4; i++)
        #pragma unroll
        for (int j = 0; j < 4; j++)
            #pragma unroll
            for (int r = 0; r < 4; r++) acc[i][j][r] = 0.f;

    const int lrow = t >> 3;                   // 0..31
    const int lseg = (t & 7) * 8;              // bf16 col within 64-chunk

    auto issue_load = [&](int c) {
        const int p = c / KC, kb = c - p * KC;
        const bf16* Ap = (p == 2) ? A2 : A1;
        const bf16* Bp = (p == 1) ? B2 : B1;
        const uint32_t abase = sbase + (uint32_t)(c & 1) * TILE_B;
        const uint32_t bbase = abase + 18432;
        const size_t kEl = (size_t)(kb << 6) + lseg;
        #pragma unroll
        for (int i = 0; i < 4; i++) {
            const int row = lrow + i * 32;
            const uint32_t ad = abase + row * ROWSTR + lseg * 2;
            const bf16* as = Ap + (size_t)(m0 + row) * Kglob + kEl;
            asm volatile("cp.async.cg.shared.global [%0], [%1], 16;" :: "r"(ad), "l"(as));
            const uint32_t bd = bbase + row * ROWSTR + lseg * 2;
            const bf16* bs = Bp + (size_t)(n0 + row) * Kglob + kEl;
            asm volatile("cp.async.cg.shared.global [%0], [%1], 16;" :: "r"(bd), "l"(bs));
        }
        asm volatile("cp.async.commit_group;" ::: "memory");
    };

    issue_load(0);

    for (int c = 0; c < TOT; c++) {
        if (c + 1 < TOT) {
            issue_load(c + 1);
            asm volatile("cp.async.wait_group 1;" ::: "memory");
        } else {
            asm volatile("cp.async.wait_group 0;" ::: "memory");
        }
        __syncthreads();

        const uint32_t abase = sbase + (uint32_t)(c & 1) * TILE_B;
        const uint32_t bbase = abase + 18432;
        const int acol = ((lane >> 4) * 8) * 2;          // byte col offset within k16
        const int arow = (lane & 15);
        const int brow = (lane & 7) + ((lane >> 3) & 1) * 8;

        #pragma unroll
        for (int kk = 0; kk < 4; kk++) {
            const int kbyte = kk * 32 + acol;
            uint32_t a[4][4];
            #pragma unroll
            for (int mf = 0; mf < 4; mf++) {
                const uint32_t ad = abase + (wm * 64 + mf * 16 + arow) * ROWSTR + kbyte;
                asm volatile("ldmatrix.sync.aligned.m8n8.x4.shared.b16 {%0,%1,%2,%3}, [%4];"
                    : "=r"(a[mf][0]), "=r"(a[mf][1]), "=r"(a[mf][2]), "=r"(a[mf][3]) : "r"(ad));
            }
            uint32_t b[4][2];
            #pragma unroll
            for (int nfp = 0; nfp < 2; nfp++) {
                const uint32_t bd = bbase + (wn * 32 + nfp * 16 + brow) * ROWSTR + kbyte;
                uint32_t r0, r1, r2, r3;
                asm volatile("ldmatrix.sync.aligned.m8n8.x4.shared.b16 {%0,%1,%2,%3}, [%4];"
                    : "=r"(r0), "=r"(r1), "=r"(r2), "=r"(r3) : "r"(bd));
                b[nfp * 2 + 0][0] = r0; b[nfp * 2 + 0][1] = r2;
                b[nfp * 2 + 1][0] = r1; b[nfp * 2 + 1][1] = r3;
            }
            #pragma unroll
            for (int mf = 0; mf < 4; mf++)
                #pragma unroll
                for (int nf = 0; nf < 4; nf++)
                    asm volatile(
                        "mma.sync.aligned.m16n8k16.row.col.f32.bf16.bf16.f32 "
                        "{%0,%1,%2,%3}, {%4,%5,%6,%7}, {%8,%9}, {%0,%1,%2,%3};"
                        : "+f"(acc[mf][nf][0]), "+f"(acc[mf][nf][1]),
                          "+f"(acc[mf][nf][2]), "+f"(acc[mf][nf][3])
                        : "r"(a[mf][0]), "r"(a[mf][1]), "r"(a[mf][2]), "r"(a[mf][3]),
                          "r"(b[nf][0]), "r"(b[nf][1]));
        }
        __syncthreads();
    }

    // ---------------- epilogue ----------------
    const int gr = lane >> 2;
    const int gc = (lane & 3) * 2;
    float hs = 0.f;

    #pragma unroll
    for (int mf = 0; mf < 4; mf++) {
        #pragma unroll
        for (int nf = 0; nf < 4; nf++) {
            const int col = n0 + wn * 32 + nf * 8 + gc;
            #pragma unroll
            for (int half = 0; half < 2; half++) {
                const int row = m0 + wm * 64 + mf * 16 + gr + half * 8;
                const float va = acc[mf][nf][half * 2];
                const float vb = acc[mf][nf][half * 2 + 1];
                if (EPI == 1) {
                    const int h_ = col >> 6, q_ = col & 63;
                    const int b_ = row >> 10, n_ = row & 1023;
                    float2 v = make_float2(va, vb);
                    *(float2*)&C[(((size_t)(b_ * Hh + h_)) * Nn + n_) * QKd + q_] = v;
                } else if (EPI == 2) {
                    const size_t off = (size_t)row * Ncols + col;
                    const float v0 = fmaxf(va, 0.f), v1 = fmaxf(vb, 0.f);
                    hs = fmaf(v0, v0, fmaf(v1, v1, hs));
                    bf16 h0, l0, h1, l1;
                    split2(v0, h0, l0); split2(v1, h1, l1);
                    bf16 hh[2] = {h0, h1}, ll[2] = {l0, l1};
                    *(uint32_t*)(O1 + off) = *(const uint32_t*)hh;
                    *(uint32_t*)(O2 + off) = *(const uint32_t*)ll;
                } else {
                    const size_t off = (size_t)row * Ncols + col;
                    float2 v = make_float2(va * alpha, vb * alpha);
                    if (accFlag) {
                        float2 o = *(const float2*)&C[off];
                        v.x += o.x; v.y += o.y;
                    }
                    *(float2*)&C[off] = v;
                }
            }
        }
    }
    if (EPI == 2) {
        sred[t] = (double)hs;
        __syncthreads();
        for (int o = 128; o > 0; o >>= 1) { if (t < o) sred[t] += sred[t + o]; __syncthreads(); }
        if (t == 0) part[blockIdx.y * gridDim.x + blockIdx.x] = sred[0];
    }
}

// ============================================================================
// Attention pass 1: S[bh][n][m] = BETA * <Q_bh[n], K_bh[m]>, + streaming rowmax.
// ============================================================================
__global__ void __launch_bounds__(256) att_s_rowmax(
    const float* __restrict__ Qg, const float* __restrict__ Kg,
    float* __restrict__ S, float* __restrict__ rowmax)
{
    const int bh = blockIdx.y;
    const int n0 = blockIdx.x * 64;
    const float* Q = Qg + (size_t)bh * Nn * QKd;
    const float* K = Kg + (size_t)bh * Nn * QKd;
    float* Srow = S + ((size_t)bh * Nn + n0) * Nn;

    __shared__ float Qs[64][68];
    __shared__ float Kst[64][68];
    __shared__ float red[64][17];
    __shared__ float rmaxS[64];

    const int t = threadIdx.x;
    const int ty = t >> 4, tx = t & 15;

    #pragma unroll
    for (int i = 0; i < 16; i++) {
        int l = i * 256 + t; int r = l >> 6, cc = l & 63;
        Qs[r][cc] = Q[(size_t)(n0 + r) * QKd + cc];
    }
    if (t < 64) rmaxS[t] = -CUDART_INF_F;
    __syncthreads();

    for (int kt = 0; kt < 16; kt++) {
        #pragma unroll
        for (int i = 0; i < 16; i++) {
            int l = i * 256 + t; int m = l >> 6, q = l & 63;
            Kst[q][m] = K[(size_t)(kt * 64 + m) * QKd + q];
        }
        __syncthreads();

        float c_[4][4] = {};
        #pragma unroll
        for (int q = 0; q < 64; q += 4) {
            float a[4][4], b[4][4];
            #pragma unroll
            for (int i = 0; i < 4; i++)
                *(float4*)&a[i][0] = *(const float4*)&Qs[ty * 4 + i][q];
            #pragma unroll
            for (int r = 0; r < 4; r++)
                *(float4*)&b[r][0] = *(const float4*)&Kst[q + r][tx * 4];
            #pragma unroll
            for (int i = 0; i < 4; i++)
                #pragma unroll
                for (int j = 0; j < 4; j++)
                    c_[i][j] += a[i][0] * b[0][j] + a[i][1] * b[1][j]
                              + a[i][2] * b[2][j] + a[i][3] * b[3][j];
        }

        #pragma unroll
        for (int i = 0; i < 4; i++) {
            float4 v = make_float4(c_[i][0] * BETA, c_[i][1] * BETA,
                                   c_[i][2] * BETA, c_[i][3] * BETA);
            *(float4*)&Srow[(size_t)(ty * 4 + i) * Nn + kt * 64 + tx * 4] = v;
            red[ty * 4 + i][tx] = fmaxf(fmaxf(v.x, v.y), fmaxf(v.z, v.w));
        }
        __syncthreads();
        if (t < 64) {
            float m = rmaxS[t];
            #pragma unroll
            for (int j = 0; j < 16; j++) m = fmaxf(m, red[t][j]);
            rmaxS[t] = m;
        }
        __syncthreads();
    }
    if (t < 64) rowmax[bh * Nn + n0 + t] = rmaxS[t];
}

// ============================================================================
// Convert: S <- exp(S - rowmax[n]) in place; inv[n] = 1/rowsum; lse partials.
// ============================================================================
__global__ void __launch_bounds__(256) att_convert(
    float* __restrict__ S, const float* __restrict__ rowmax,
    float* __restrict__ inv, double* __restrict__ lse_part)
{
    const int bh = blockIdx.y;
    const int r0 = blockIdx.x * 16;
    const int t = threadIdx.x;
    const int rloc = t >> 4, lane = t & 15;
    const int row = r0 + rloc;
    const float rm = rowmax[bh * Nn + row];
    float* Sr = S + ((size_t)bh * Nn + row) * Nn;

    float sum = 0.f;
    #pragma unroll 4
    for (int i = 0; i < 64; i++) {
        int c = i * 16 + lane;
        float e = __expf(Sr[c] - rm);
        Sr[c] = e;
        sum += e;
    }
    #pragma unroll
    for (int o = 8; o > 0; o >>= 1) sum += __shfl_xor_sync(0xffffffffu, sum, o);

    __shared__ double part[16];
    if (lane == 0) {
        inv[bh * Nn + row] = 1.f / sum;
        part[rloc] = (double)rm + (double)logf(sum);
    }
    __syncthreads();
    if (t == 0) {
        double s = 0.0;
        #pragma unroll
        for (int i = 0; i < 16; i++) s += part[i];
        lse_part[bh * (Nn / 16) + blockIdx.x] = s;
    }
}

// ============================================================================
// dQ[bh][n][q] = -inv[n] * sum_m P'[n][m] * K[bh][m][q]
// ============================================================================
__global__ void __launch_bounds__(256) att_dq(
    const float* __restrict__ P, const float* __restrict__ Kg,
    const float* __restrict__ inv, float* __restrict__ dQ)
{
    const int bh = blockIdx.y;
    const int n0 = blockIdx.x * 64;
    const float* Pg = P + ((size_t)bh * Nn + n0) * Nn;
    const float* K = Kg + (size_t)bh * Nn * QKd;
    __shared__ float Ps[64][68];
    __shared__ float Ks[64][64];
    const int t = threadIdx.x, ty = t >> 4, tx = t & 15;
    float acc[4][4] = {};

    for (int kt = 0; kt < 16; kt++) {
        #pragma unroll
        for (int i = 0; i < 16; i++) {
            int l = i * 256 + t; int r = l >> 6, c = l & 63;
            Ps[r][c] = Pg[(size_t)r * Nn + kt * 64 + c];
            Ks[r][c] = K[(size_t)(kt * 64 + r) * QKd + c];
        }
        __syncthreads();
        #pragma unroll
        for (int m = 0; m < 64; m += 4) {
            float a[4][4], b[4][4];
            #pragma unroll
            for (int i = 0; i < 4; i++)
                *(float4*)&a[i][0] = *(const float4*)&Ps[ty * 4 + i][m];
            #pragma unroll
            for (int r = 0; r < 4; r++)
                *(float4*)&b[r][0] = *(const float4*)&Ks[m + r][tx * 4];
            #pragma unroll
            for (int i = 0; i < 4; i++)
                #pragma unroll
                for (int j = 0; j < 4; j++)
                    acc[i][j] += a[i][0] * b[0][j] + a[i][1] * b[1][j]
                               + a[i][2] * b[2][j] + a[i][3] * b[3][j];
        }
        __syncthreads();
    }
    #pragma unroll
    for (int i = 0; i < 4; i++) {
        int n = n0 + ty * 4 + i;
        float s = -inv[bh * Nn + n];
        float4 v = make_float4(acc[i][0] * s, acc[i][1] * s, acc[i][2] * s, acc[i][3] * s);
        *(float4*)&dQ[((size_t)bh * Nn + n) * QKd + tx * 4] = v;
    }
}

// ============================================================================
// dK[bh][m][q] = -sum_n (P'[n][m] * inv[n]) * Q[bh][n][q]
// ============================================================================
__global__ void __launch_bounds__(256) att_dk(
    const float* __restrict__ P, const float* __restrict__ Qg,
    const float* __restrict__ inv, float* __restrict__ dK)
{
    const int bh = blockIdx.y;
    const int m0 = blockIdx.x * 64;
    const float* Q = Qg + (size_t)bh * Nn * QKd;
    __shared__ float Ps[64][68];
    __shared__ float Qs[64][64];
    __shared__ float invs[64];
    const int t = threadIdx.x, ty = t >> 4, tx = t & 15;
    float acc[4][4] = {};

    for (int nt = 0; nt < 16; nt++) {
        if (t < 64) invs[t] = inv[bh * Nn + nt * 64 + t];
        __syncthreads();
        #pragma unroll
        for (int i = 0; i < 16; i++) {
            int l = i * 256 + t; int r = l >> 6, c = l & 63;
            Ps[r][c] = P[((size_t)bh * Nn + nt * 64 + r) * Nn + m0 + c] * invs[r];
            Qs[r][c] = Q[(size_t)(nt * 64 + r) * QKd + c];
        }
        __syncthreads();
        #pragma unroll
        for (int n = 0; n < 64; n += 4) {
            float a[4][4], b[4][4];
            #pragma unroll
            for (int r = 0; r < 4; r++) {
                *(float4*)&a[r][0] = *(const float4*)&Ps[n + r][ty * 4];
                *(float4*)&b[r][0] = *(const float4*)&Qs[n + r][tx * 4];
            }
            #pragma unroll
            for (int i = 0; i < 4; i++)
                #pragma unroll
                for (int j = 0; j < 4; j++)
                    acc[i][j] += a[0][i] * b[0][j] + a[1][i] * b[1][j]
                               + a[2][i] * b[2][j] + a[3][i] * b[3][j];
        }
        __syncthreads();
    }
    #pragma unroll
    for (int i = 0; i < 4; i++) {
        int m = m0 + ty * 4 + i;
        float4 v = make_float4(-acc[i][0], -acc[i][1], -acc[i][2], -acc[i][3]);
        *(float4*)&dK[((size_t)bh * Nn + m) * QKd + tx * 4] = v;
    }
}

// ============================================================================
// Repack dQ/dK [bh][n][qk] -> bf16 split planes [b*n][h*qk]
// ============================================================================
__global__ void __launch_bounds__(256) repack_split(
    const float* __restrict__ dQb, const float* __restrict__ dKb,
    bf16* __restrict__ q1, bf16* __restrict__ q2,
    bf16* __restrict__ k1, bf16* __restrict__ k2)
{
    int idx = blockIdx.x * 256 + threadIdx.x;
    int q = idx & 63;
    int h = (idx >> 6) & 15;
    int n = (idx >> 10) & 1023;
    int b = idx >> 20;
    size_t src = (((size_t)(b * Hh + h) * Nn) + n) * QKd + q;
    bf16 hh, ll;
    split2(dQb[src], hh, ll); q1[idx] = hh; q2[idx] = ll;
    split2(dKb[src], hh, ll); k1[idx] = hh; k2[idx] = ll;
}

// ============================================================================
// Final energy: E = -(1/BETA) * sum(lse) - 0.5 * sum(h^2). Deterministic.
// ============================================================================
__global__ void energy_final(const double* __restrict__ lse_part,
                             const double* __restrict__ h2_part,
                             float* __restrict__ out)
{
    __shared__ double sm[256];
    int t = threadIdx.x;
    double s = 0.0;
    for (int i = t; i < BH * (Nn / 16); i += 256) s += lse_part[i];
    double s2 = 0.0;
    for (int i = t; i < (BNr / 128) * (HIDd / 128); i += 256) s2 += h2_part[i];
    sm[t] = -8.0 * s - 0.5 * s2;
    __syncthreads();
    for (int o = 128; o > 0; o >>= 1) { if (t < o) sm[t] += sm[t + o]; __syncthreads(); }
    if (t == 0) out[(size_t)BNr * Dd] = (float)sm[0];
}

// ============================================================================
// Host launcher
// ============================================================================
extern "C" void kernel_launch(void* const* d_in, const int* in_sizes, int n_in,
                              void* d_out, int out_size)
{
    const float* x    = (const float*)d_in[0];   // [B,N,D]
    const float* Wq   = (const float*)d_in[1];   // [H,QK,D] -> flat [HQ, D]
    const float* Wk   = (const float*)d_in[2];
    const float* Whop = (const float*)d_in[3];   // [D, HID]
    float* out = (float*)d_out;

    float *pQ, *pK, *pdQ, *pdK, *pS, *pRM, *pINV;
    double *pLse, *pH2;
    bf16 *px1, *px2, *pwq1, *pwq2, *pwk1, *pwk2, *pwqt1, *pwqt2, *pwkt1, *pwkt2;
    bf16 *pwh1, *pwh2, *pwht1, *pwht2, *phb1, *phb2, *pdq1, *pdq2, *pdk1, *pdk2;

    cudaGetSymbolAddress((void**)&pQ,   g_Q);
    cudaGetSymbolAddress((void**)&pK,   g_K);
    cudaGetSymbolAddress((void**)&pdQ,  g_dQ);
    cudaGetSymbolAddress((void**)&pdK,  g_dK);
    cudaGetSymbolAddress((void**)&pS,   g_S);
    cudaGetSymbolAddress((void**)&pRM,  g_rowmax);
    cudaGetSymbolAddress((void**)&pINV, g_inv);
    cudaGetSymbolAddress((void**)&pLse, g_lse_part);
    cudaGetSymbolAddress((void**)&pH2,  g_h2_part);
    cudaGetSymbolAddress((void**)&px1,  g_x1);  cudaGetSymbolAddress((void**)&px2,  g_x2);
    cudaGetSymbolAddress((void**)&pwq1, g_wq1); cudaGetSymbolAddress((void**)&pwq2, g_wq2);
    cudaGetSymbolAddress((void**)&pwk1, g_wk1); cudaGetSymbolAddress((void**)&pwk2, g_wk2);
    cudaGetSymbolAddress((void**)&pwqt1,g_wqt1);cudaGetSymbolAddress((void**)&pwqt2,g_wqt2);
    cudaGetSymbolAddress((void**)&pwkt1,g_wkt1);cudaGetSymbolAddress((void**)&pwkt2,g_wkt2);
    cudaGetSymbolAddress((void**)&pwh1, g_wh1); cudaGetSymbolAddress((void**)&pwh2, g_wh2);
    cudaGetSymbolAddress((void**)&pwht1,g_wht1);cudaGetSymbolAddress((void**)&pwht2,g_wht2);
    cudaGetSymbolAddress((void**)&phb1, g_hb1); cudaGetSymbolAddress((void**)&phb2, g_hb2);
    cudaGetSymbolAddress((void**)&pdq1, g_dqm1);cudaGetSymbolAddress((void**)&pdq2, g_dqm2);
    cudaGetSymbolAddress((void**)&pdk1, g_dkm1);cudaGetSymbolAddress((void**)&pdk2, g_dkm2);

    cudaFuncSetAttribute(tgemm<0>, cudaFuncAttributeMaxDynamicSharedMemorySize, TG_SMEM);
    cudaFuncSetAttribute(tgemm<1>, cudaFuncAttributeMaxDynamicSharedMemorySize, TG_SMEM);
    cudaFuncSetAttribute(tgemm<2>, cudaFuncAttributeMaxDynamicSharedMemorySize, TG_SMEM);

    dim3 blk(256);

    // 0. bf16 splits of inputs
    split_plain<<<(BNr * Dd) / 256, blk>>>(x, px1, px2);
    split_plain<<<(HQ * Dd) / 256, blk>>>(Wq, pwq1, pwq2);
    split_plain<<<(HQ * Dd) / 256, blk>>>(Wk, pwk1, pwk2);
    split_plain<<<(Dd * HIDd) / 256, blk>>>(Whop, pwh1, pwh2);
    split_trans<<<(HQ * Dd) / 256, blk>>>(Wq, pwqt1, pwqt2, HQ, Dd);
    split_trans<<<(HQ * Dd) / 256, blk>>>(Wk, pwkt1, pwkt2, HQ, Dd);
    split_trans<<<(Dd * HIDd) / 256, blk>>>(Whop, pwht1, pwht2, Dd, HIDd);

    // 1-2. Q = X Wq^T, K = X Wk^T  (HMMA, scatter to [bh][n][qk])
    tgemm<1><<<dim3(HQ / 128, BNr / 128), blk, TG_SMEM>>>(
        px1, px2, pwq1, pwq2, pQ, HQ, Dd, 1.f, 0, nullptr, nullptr, nullptr);
    tgemm<1><<<dim3(HQ / 128, BNr / 128), blk, TG_SMEM>>>(
        px1, px2, pwk1, pwk2, pK, HQ, Dd, 1.f, 0, nullptr, nullptr, nullptr);

    // 3-6. attention (scalar fp32)
    att_s_rowmax<<<dim3(Nn / 64, BH), blk>>>(pQ, pK, pS, pRM);
    att_convert<<<dim3(Nn / 16, BH), blk>>>(pS, pRM, pINV, pLse);
    att_dq<<<dim3(Nn / 64, BH), blk>>>(pS, pK, pINV, pdQ);
    att_dk<<<dim3(Nn / 64, BH), blk>>>(pS, pQ, pINV, pdK);

    // 7. repack + split dQ/dK
    repack_split<<<(BNr * HQ) / 256, blk>>>(pdQ, pdK, pdq1, pdq2, pdk1, pdk2);

    // 8-9. grad = dQm @ Wq + dKm @ Wk   (HMMA; B = W^T planes [D, HQ])
    tgemm<0><<<dim3(Dd / 128, BNr / 128), blk, TG_SMEM>>>(
        pdq1, pdq2, pwqt1, pwqt2, out, Dd, HQ, 1.f, 0, nullptr, nullptr, nullptr);
    tgemm<0><<<dim3(Dd / 128, BNr / 128), blk, TG_SMEM>>>(
        pdk1, pdk2, pwkt1, pwkt2, out, Dd, HQ, 1.f, 1, nullptr, nullptr, nullptr);

    // 10. Hb = relu(X @ W_hop) (HMMA; B = Whop^T planes [HID, D]); h2 partials
    tgemm<2><<<dim3(HIDd / 128, BNr / 128), blk, TG_SMEM>>>(
        px1, px2, pwht1, pwht2, nullptr, HIDd, Dd, 1.f, 0, phb1, phb2, pH2);

    // 11. grad -= Hb @ W_hop^T  (HMMA; B = Whop planes [D, HID], K = HID)
    tgemm<0><<<dim3(Dd / 128, BNr / 128), blk, TG_SMEM>>>(
        phb1, phb2, pwh1, pwh2, out, Dd, HIDd, -1.f, 1, nullptr, nullptr, nullptr);

    // 12. energy scalar
    if (out_size > BNr * Dd)
        energy_final<<<1, 256>>>(pLse, pH2, out);
}

// round 9
// speedup vs baseline: 2.4096x; 1.3789x over previous
#include <cuda_runtime.h>
#include <cuda_bf16.h>
#include <math_constants.h>
#include <cstdint>

#define Bsz 4
#define Nn 1024
#define Dd 1024
#define Hh 16
#define QKd 64
#define HIDd 4096
#define BH 64           // B*H
#define BNr 4096        // B*N
#define HQ 1024         // H*QK
#define BETA 0.125f

typedef unsigned long long u64;
typedef __nv_bfloat16 bf16;

__device__ __forceinline__ uint32_t smem_u32(const void* p) {
    uint32_t a;
    asm("{ .reg .u64 t; cvta.to.shared.u64 t, %1; cvt.u32.u64 %0, t; }" : "=r"(a) : "l"(p));
    return a;
}
__device__ __forceinline__ void split2(float v, bf16& h, bf16& l) {
    h = __float2bfloat16(v);
    l = __float2bfloat16(v - __bfloat162float(h));
}

// -------- device scratch (static allocation; no cudaMalloc anywhere) --------
__device__ float  g_Q  [(size_t)BH * Nn * QKd];   // [bh][n][qk] fp32
__device__ float  g_K  [(size_t)BH * Nn * QKd];
__device__ float  g_dQ [(size_t)BH * Nn * QKd];
__device__ float  g_dK [(size_t)BH * Nn * QKd];
__device__ float  g_S  [(size_t)BH * Nn * Nn];    // beta * scores (fp32, 256MB)
__device__ bf16   g_P  [(size_t)BH * Nn * Nn];    // softmax probs (bf16, 128MB)
__device__ double g_lse_part[BH * (Nn / 16)];
__device__ double g_h2_part [(BNr / 128) * (HIDd / 128)];

// bf16 split planes
__device__ bf16 g_x1 [(size_t)BNr * Dd],   g_x2 [(size_t)BNr * Dd];
__device__ bf16 g_wq1[(size_t)HQ * Dd],    g_wq2[(size_t)HQ * Dd];
__device__ bf16 g_wk1[(size_t)HQ * Dd],    g_wk2[(size_t)HQ * Dd];
__device__ bf16 g_wqt1[(size_t)Dd * HQ],   g_wqt2[(size_t)Dd * HQ];
__device__ bf16 g_wkt1[(size_t)Dd * HQ],   g_wkt2[(size_t)Dd * HQ];
__device__ bf16 g_wh1[(size_t)Dd * HIDd],  g_wh2[(size_t)Dd * HIDd];
__device__ bf16 g_wht1[(size_t)HIDd * Dd], g_wht2[(size_t)HIDd * Dd];
__device__ bf16 g_hb1[(size_t)BNr * HIDd], g_hb2[(size_t)BNr * HIDd];
__device__ bf16 g_dqm1[(size_t)BNr * HQ],  g_dqm2[(size_t)BNr * HQ];
__device__ bf16 g_dkm1[(size_t)BNr * HQ],  g_dkm2[(size_t)BNr * HQ];
// attention operands
__device__ bf16 g_q1[(size_t)BH * Nn * QKd], g_q2[(size_t)BH * Nn * QKd];
__device__ bf16 g_k1[(size_t)BH * Nn * QKd], g_k2[(size_t)BH * Nn * QKd];
__device__ bf16 g_qt[(size_t)BH * QKd * Nn], g_kt[(size_t)BH * QKd * Nn];

// ============================================================================
// Split kernels: fp32 -> (hi, lo) bf16 planes
// ============================================================================
__global__ void __launch_bounds__(256) split_plain(
    const float* __restrict__ in, bf16* __restrict__ o1, bf16* __restrict__ o2)
{
    size_t i = (size_t)blockIdx.x * 256 + threadIdx.x;
    bf16 h, l; split2(in[i], h, l);
    o1[i] = h; o2[i] = l;
}
__global__ void __launch_bounds__(256) split_trans(
    const float* __restrict__ in, bf16* __restrict__ o1, bf16* __restrict__ o2,
    int R, int Ccols)
{
    size_t idx = (size_t)blockIdx.x * 256 + threadIdx.x;
    int r = (int)(idx % R);
    int c = (int)(idx / R);
    bf16 h, l; split2(in[(size_t)r * Ccols + c], h, l);
    o1[idx] = h; o2[idx] = l;
}

// ============================================================================
// Tiled transpose: Q,K fp32 [bh][n][qk] -> Qt,Kt bf16 [bh][qk][n]
// ============================================================================
__global__ void __launch_bounds__(256) trans_qk(
    const float* __restrict__ Q, const float* __restrict__ K,
    bf16* __restrict__ Qt, bf16* __restrict__ Kt)
{
    __shared__ float tq[32][33], tk[32][33];
    const int n0 = blockIdx.x * 32, q0 = blockIdx.y * 32, bh = blockIdx.z;
    const float* Qb = Q + (size_t)bh * Nn * QKd;
    const float* Kb = K + (size_t)bh * Nn * QKd;
    const int tx = threadIdx.x & 31, ty = threadIdx.x >> 5;   // 32 x 8
    #pragma unroll
    for (int i = 0; i < 4; i++) {
        int n = ty + i * 8;
        tq[n][tx] = Qb[(size_t)(n0 + n) * QKd + q0 + tx];
        tk[n][tx] = Kb[(size_t)(n0 + n) * QKd + q0 + tx];
    }
    __syncthreads();
    #pragma unroll
    for (int i = 0; i < 4; i++) {
        int r = ty + i * 8;
        Qt[((size_t)bh * QKd + q0 + r) * Nn + n0 + tx] = __float2bfloat16(tq[tx][r]);
        Kt[((size_t)bh * QKd + q0 + r) * Nn + n0 + tx] = __float2bfloat16(tk[tx][r]);
    }
}

// ============================================================================
// HMMA bf16x2 GEMM: C[m,n] = alpha * sum_k A[m,k]*B[n,k]  (3-sweep hi/lo split)
// Batched via blockIdx.z (element strides zsA/zsB/zsC).
//   EPI=0: C (+)= alpha*D    EPI=1: scatter to [bh][n][qk]
//   EPI=2: relu; bf16-split to O1/O2; sum(v^2) partials to part
// ============================================================================
#define TILE_B 36864
#define ROWSTR 144
#define TG_SMEM (2 * TILE_B)

template<int EPI>
__global__ void __launch_bounds__(256) tgemm(
    const bf16* __restrict__ A1, const bf16* __restrict__ A2,
    const bf16* __restrict__ B1, const bf16* __restrict__ B2,
    float* __restrict__ C, int Ncols, int Kglob, float alpha, int accFlag,
    bf16* __restrict__ O1, bf16* __restrict__ O2, double* __restrict__ part,
    size_t zsA, size_t zsB, size_t zsC)
{
    extern __shared__ char dsm[];
    __shared__ double sred[256];
    const uint32_t sbase = smem_u32(dsm);

    const size_t zA = (size_t)blockIdx.z * zsA;
    const size_t zB = (size_t)blockIdx.z * zsB;
    A1 += zA; A2 += zA; B1 += zB; B2 += zB; C += (size_t)blockIdx.z * zsC;

    const int t = threadIdx.x;
    const int wid = t >> 5, lane = t & 31;
    const int m0 = blockIdx.y * 128, n0 = blockIdx.x * 128;
    const int wm = wid >> 2, wn = wid & 3;

    const int KC = Kglob >> 6;
    const int TOT = 3 * KC;

    float acc[4][4][4];
    #pragma unroll
    for (int i = 0; i < 4; i++)
        #pragma unroll
        for (int j = 0; j < 4; j++)
            #pragma unroll
            for (int r = 0; r < 4; r++) acc[i][j][r] = 0.f;

    const int lrow = t >> 3;
    const int lseg = (t & 7) * 8;

    auto issue_load = [&](int c) {
        const int p = c / KC, kb = c - p * KC;
        const bf16* Ap = (p == 2) ? A2 : A1;
        const bf16* Bp = (p == 1) ? B2 : B1;
        const uint32_t abase = sbase + (uint32_t)(c & 1) * TILE_B;
        const uint32_t bbase = abase + 18432;
        const size_t kEl = (size_t)(kb << 6) + lseg;
        #pragma unroll
        for (int i = 0; i < 4; i++) {
            const int row = lrow + i * 32;
            const uint32_t ad = abase + row * ROWSTR + lseg * 2;
            const bf16* as = Ap + (size_t)(m0 + row) * Kglob + kEl;
            asm volatile("cp.async.cg.shared.global [%0], [%1], 16;" :: "r"(ad), "l"(as));
            const uint32_t bd = bbase + row * ROWSTR + lseg * 2;
            const bf16* bs = Bp + (size_t)(n0 + row) * Kglob + kEl;
            asm volatile("cp.async.cg.shared.global [%0], [%1], 16;" :: "r"(bd), "l"(bs));
        }
        asm volatile("cp.async.commit_group;" ::: "memory");
    };

    issue_load(0);

    for (int c = 0; c < TOT; c++) {
        if (c + 1 < TOT) {
            issue_load(c + 1);
            asm volatile("cp.async.wait_group 1;" ::: "memory");
        } else {
            asm volatile("cp.async.wait_group 0;" ::: "memory");
        }
        __syncthreads();

        const uint32_t abase = sbase + (uint32_t)(c & 1) * TILE_B;
        const uint32_t bbase = abase + 18432;
        const int acol = ((lane >> 4) * 8) * 2;
        const int arow = (lane & 15);
        const int brow = (lane & 7) + ((lane >> 3) & 1) * 8;

        #pragma unroll
        for (int kk = 0; kk < 4; kk++) {
            const int kbyte = kk * 32 + acol;
            uint32_t a[4][4];
            #pragma unroll
            for (int mf = 0; mf < 4; mf++) {
                const uint32_t ad = abase + (wm * 64 + mf * 16 + arow) * ROWSTR + kbyte;
                asm volatile("ldmatrix.sync.aligned.m8n8.x4.shared.b16 {%0,%1,%2,%3}, [%4];"
                    : "=r"(a[mf][0]), "=r"(a[mf][1]), "=r"(a[mf][2]), "=r"(a[mf][3]) : "r"(ad));
            }
            uint32_t b[4][2];
            #pragma unroll
            for (int nfp = 0; nfp < 2; nfp++) {
                const uint32_t bd = bbase + (wn * 32 + nfp * 16 + brow) * ROWSTR + kbyte;
                uint32_t r0, r1, r2, r3;
                asm volatile("ldmatrix.sync.aligned.m8n8.x4.shared.b16 {%0,%1,%2,%3}, [%4];"
                    : "=r"(r0), "=r"(r1), "=r"(r2), "=r"(r3) : "r"(bd));
                b[nfp * 2 + 0][0] = r0; b[nfp * 2 + 0][1] = r2;
                b[nfp * 2 + 1][0] = r1; b[nfp * 2 + 1][1] = r3;
            }
            #pragma unroll
            for (int mf = 0; mf < 4; mf++)
                #pragma unroll
                for (int nf = 0; nf < 4; nf++)
                    asm volatile(
                        "mma.sync.aligned.m16n8k16.row.col.f32.bf16.bf16.f32 "
                        "{%0,%1,%2,%3}, {%4,%5,%6,%7}, {%8,%9}, {%0,%1,%2,%3};"
                        : "+f"(acc[mf][nf][0]), "+f"(acc[mf][nf][1]),
                          "+f"(acc[mf][nf][2]), "+f"(acc[mf][nf][3])
                        : "r"(a[mf][0]), "r"(a[mf][1]), "r"(a[mf][2]), "r"(a[mf][3]),
                          "r"(b[nf][0]), "r"(b[nf][1]));
        }
        __syncthreads();
    }

    const int gr = lane >> 2;
    const int gc = (lane & 3) * 2;
    float hs = 0.f;

    #pragma unroll
    for (int mf = 0; mf < 4; mf++) {
        #pragma unroll
        for (int nf = 0; nf < 4; nf++) {
            const int col = n0 + wn * 32 + nf * 8 + gc;
            #pragma unroll
            for (int half = 0; half < 2; half++) {
                const int row = m0 + wm * 64 + mf * 16 + gr + half * 8;
                const float va = acc[mf][nf][half * 2];
                const float vb = acc[mf][nf][half * 2 + 1];
                if (EPI == 1) {
                    const int h_ = col >> 6, q_ = col & 63;
                    const int b_ = row >> 10, n_ = row & 1023;
                    float2 v = make_float2(va, vb);
                    *(float2*)&C[(((size_t)(b_ * Hh + h_)) * Nn + n_) * QKd + q_] = v;
                } else if (EPI == 2) {
                    const size_t off = (size_t)row * Ncols + col;
                    const float v0 = fmaxf(va, 0.f), v1 = fmaxf(vb, 0.f);
                    hs = fmaf(v0, v0, fmaf(v1, v1, hs));
                    bf16 h0, l0, h1, l1;
                    split2(v0, h0, l0); split2(v1, h1, l1);
                    bf16 hh[2] = {h0, h1}, ll[2] = {l0, l1};
                    *(uint32_t*)(O1 + off) = *(const uint32_t*)hh;
                    *(uint32_t*)(O2 + off) = *(const uint32_t*)ll;
                } else {
                    const size_t off = (size_t)row * Ncols + col;
                    float2 v = make_float2(va * alpha, vb * alpha);
                    if (accFlag) {
                        float2 o = *(const float2*)&C[off];
                        v.x += o.x; v.y += o.y;
                    }
                    *(float2*)&C[off] = v;
                }
            }
        }
    }
    if (EPI == 2) {
        sred[t] = (double)hs;
        __syncthreads();
        for (int o = 128; o > 0; o >>= 1) { if (t < o) sred[t] += sred[t + o]; __syncthreads(); }
        if (t == 0) part[blockIdx.y * gridDim.x + blockIdx.x] = sred[0];
    }
}

// ============================================================================
// Convert (3-pass): rowmax, rowsum, write P' = softmax bf16; lse partials.
// grid (Nn/16, BH), 256 threads = 16 rows x 16 lanes.
// ============================================================================
__global__ void __launch_bounds__(256) att_convert3(
    const float* __restrict__ S, bf16* __restrict__ P, double* __restrict__ lse_part)
{
    const int bh = blockIdx.y;
    const int r0 = blockIdx.x * 16;
    const int t = threadIdx.x;
    const int rloc = t >> 4, lane = t & 15;
    const int row = r0 + rloc;
    const float* Sr = S + ((size_t)bh * Nn + row) * Nn;
    bf16* Pr = P + ((size_t)bh * Nn + row) * Nn;

    float m = -CUDART_INF_F;
    #pragma unroll 4
    for (int i = 0; i < 64; i++) m = fmaxf(m, Sr[i * 16 + lane]);
    #pragma unroll
    for (int o = 8; o > 0; o >>= 1) m = fmaxf(m, __shfl_xor_sync(0xffffffffu, m, o));

    float sum = 0.f;
    #pragma unroll 4
    for (int i = 0; i < 64; i++) sum += __expf(Sr[i * 16 + lane] - m);
    #pragma unroll
    for (int o = 8; o > 0; o >>= 1) sum += __shfl_xor_sync(0xffffffffu, sum, o);

    const float inv = 1.f / sum;
    #pragma unroll 4
    for (int i = 0; i < 64; i++) {
        int c = i * 16 + lane;
        Pr[c] = __float2bfloat16(__expf(Sr[c] - m) * inv);
    }

    __shared__ double part[16];
    if (lane == 0) part[rloc] = (double)m + (double)logf(sum);
    __syncthreads();
    if (t == 0) {
        double s = 0.0;
        #pragma unroll
        for (int i = 0; i < 16; i++) s += part[i];
        lse_part[bh * (Nn / 16) + blockIdx.x] = s;
    }
}

// ============================================================================
// dQ[bh][n][q] = -sum_m P'[n][m] * Kt[q][m]   (HMMA, tile 128x64, K-chunk 64)
// ============================================================================
#define DQ_STAGE 27648   // A 128x144 + B 64x144
__global__ void __launch_bounds__(256) att_dq_h(
    const bf16* __restrict__ P, const bf16* __restrict__ Kt, float* __restrict__ dQ)
{
    extern __shared__ char dsm[];
    const uint32_t sbase = smem_u32(dsm);
    const int t = threadIdx.x, wid = t >> 5, lane = t & 31;
    const int bh = blockIdx.y, n0 = blockIdx.x * 128;
    const bf16* Ag = P + (size_t)bh * Nn * Nn;
    const bf16* Bg = Kt + (size_t)bh * QKd * Nn;

    float acc[8][4];
    #pragma unroll
    for (int i = 0; i < 8; i++)
        #pragma unroll
        for (int r = 0; r < 4; r++) acc[i][r] = 0.f;

    const int lrow = t >> 3, lseg = (t & 7) * 8;

    auto load = [&](int kb) {
        const uint32_t ab = sbase + (uint32_t)(kb & 1) * DQ_STAGE;
        const uint32_t bb = ab + 18432;
        const size_t kEl = (size_t)(kb << 6) + lseg;
        #pragma unroll
        for (int i = 0; i < 4; i++) {
            const int row = lrow + i * 32;
            asm volatile("cp.async.cg.shared.global [%0], [%1], 16;"
                :: "r"(ab + row * ROWSTR + lseg * 2), "l"(Ag + (size_t)(n0 + row) * Nn + kEl));
        }
        #pragma unroll
        for (int i = 0; i < 2; i++) {
            const int row = lrow + i * 32;
            asm volatile("cp.async.cg.shared.global [%0], [%1], 16;"
                :: "r"(bb + row * ROWSTR + lseg * 2), "l"(Bg + (size_t)row * Nn + kEl));
        }
        asm volatile("cp.async.commit_group;" ::: "memory");
    };

    load(0);
    for (int kb = 0; kb < 16; kb++) {
        if (kb < 15) { load(kb + 1); asm volatile("cp.async.wait_group 1;" ::: "memory"); }
        else         { asm volatile("cp.async.wait_group 0;" ::: "memory"); }
        __syncthreads();
        const uint32_t ab = sbase + (uint32_t)(kb & 1) * DQ_STAGE;
        const uint32_t bb = ab + 18432;
        const int acol = ((lane >> 4) * 8) * 2;
        const int arow = lane & 15;
        const int brow = (lane & 7) + ((lane >> 3) & 1) * 8;
        #pragma unroll
        for (int kk = 0; kk < 4; kk++) {
            const int kbyte = kk * 32 + acol;
            uint32_t a[4];
            asm volatile("ldmatrix.sync.aligned.m8n8.x4.shared.b16 {%0,%1,%2,%3}, [%4];"
                : "=r"(a[0]), "=r"(a[1]), "=r"(a[2]), "=r"(a[3])
                : "r"(ab + (wid * 16 + arow) * ROWSTR + kbyte));
            uint32_t b[8][2];
            #pragma unroll
            for (int nfp = 0; nfp < 4; nfp++) {
                uint32_t r0, r1, r2, r3;
                asm volatile("ldmatrix.sync.aligned.m8n8.x4.shared.b16 {%0,%1,%2,%3}, [%4];"
                    : "=r"(r0), "=r"(r1), "=r"(r2), "=r"(r3)
                    : "r"(bb + (nfp * 16 + brow) * ROWSTR + kbyte));
                b[nfp * 2 + 0][0] = r0; b[nfp * 2 + 0][1] = r2;
                b[nfp * 2 + 1][0] = r1; b[nfp * 2 + 1][1] = r3;
            }
            #pragma unroll
            for (int nf = 0; nf < 8; nf++)
                asm volatile(
                    "mma.sync.aligned.m16n8k16.row.col.f32.bf16.bf16.f32 "
                    "{%0,%1,%2,%3}, {%4,%5,%6,%7}, {%8,%9}, {%0,%1,%2,%3};"
                    : "+f"(acc[nf][0]), "+f"(acc[nf][1]), "+f"(acc[nf][2]), "+f"(acc[nf][3])
                    : "r"(a[0]), "r"(a[1]), "r"(a[2]), "r"(a[3]),
                      "r"(b[nf][0]), "r"(b[nf][1]));
        }
        __syncthreads();
    }
    const int gr = lane >> 2, gc = (lane & 3) * 2;
    #pragma unroll
    for (int nf = 0; nf < 8; nf++) {
        const int col = nf * 8 + gc;
        #pragma unroll
        for (int half = 0; half < 2; half++) {
            const int n = n0 + wid * 16 + gr + half * 8;
            float2 v = make_float2(-acc[nf][half * 2], -acc[nf][half * 2 + 1]);
            *(float2*)&dQ[((size_t)bh * Nn + n) * QKd + col] = v;
        }
    }
}

// ============================================================================
// dK[bh][m][q] = -sum_n P'[n][m] * Qt[q][n]  (HMMA; A = P'^T via ldmatrix.trans)
// ============================================================================
#define DK_ASTR 272
#define DK_STAGE 26624   // A 64x272 + B 64x144
__global__ void __launch_bounds__(256) att_dk_h(
    const bf16* __restrict__ P, const bf16* __restrict__ Qt, float* __restrict__ dK)
{
    extern __shared__ char dsm[];
    const uint32_t sbase = smem_u32(dsm);
    const int t = threadIdx.x, wid = t >> 5, lane = t & 31;
    const int bh = blockIdx.y, m0 = blockIdx.x * 128;
    const bf16* Ag = P + (size_t)bh * Nn * Nn;
    const bf16* Bg = Qt + (size_t)bh * QKd * Nn;

    float acc[8][4];
    #pragma unroll
    for (int i = 0; i < 8; i++)
        #pragma unroll
        for (int r = 0; r < 4; r++) acc[i][r] = 0.f;

    auto load = [&](int kb) {
        const uint32_t ab = sbase + (uint32_t)(kb & 1) * DK_STAGE;
        const uint32_t bb = ab + 17408;
        // A: P' rows n = kb*64..+64, cols m0..+128  -> smem [64][128] stride 272
        const int ar = t >> 4, aseg = (t & 15) * 8;
        #pragma unroll
        for (int i = 0; i < 4; i++) {
            const int row = ar + i * 16;
            asm volatile("cp.async.cg.shared.global [%0], [%1], 16;"
                :: "r"(ab + row * DK_ASTR + aseg * 2),
                   "l"(Ag + (size_t)((kb << 6) + row) * Nn + m0 + aseg));
        }
        const int br = t >> 3, bseg = (t & 7) * 8;
        #pragma unroll
        for (int i = 0; i < 2; i++) {
            const int row = br + i * 32;
            asm volatile("cp.async.cg.shared.global [%0], [%1], 16;"
                :: "r"(bb + row * ROWSTR + bseg * 2),
                   "l"(Bg + (size_t)row * Nn + (kb << 6) + bseg));
        }
        asm volatile("cp.async.commit_group;" ::: "memory");
    };

    load(0);
    for (int kb = 0; kb < 16; kb++) {
        if (kb < 15) { load(kb + 1); asm volatile("cp.async.wait_group 1;" ::: "memory"); }
        else         { asm volatile("cp.async.wait_group 0;" ::: "memory"); }
        __syncthreads();
        const uint32_t ab = sbase + (uint32_t)(kb & 1) * DK_STAGE;
        const uint32_t bb = ab + 17408;
        const int tl = lane >> 3;
        const int brow = (lane & 7) + ((lane >> 3) & 1) * 8;
        const int bcol = ((lane >> 4) * 8) * 2;
        #pragma unroll
        for (int kk = 0; kk < 4; kk++) {
            uint32_t a[4];
            // A^T load: storage [k][m]; tile (mi = tl&1, ki = tl>>1)
            const uint32_t ad = ab + (kk * 16 + (tl >> 1) * 8 + (lane & 7)) * DK_ASTR
                              + (wid * 16 + (tl & 1) * 8) * 2;
            asm volatile("ldmatrix.sync.aligned.m8n8.x4.trans.shared.b16 {%0,%1,%2,%3}, [%4];"
                : "=r"(a[0]), "=r"(a[1]), "=r"(a[2]), "=r"(a[3]) : "r"(ad));
            uint32_t b[8][2];
            const int kbyte = kk * 32 + bcol;
            #pragma unroll
            for (int nfp = 0; nfp < 4; nfp++) {
                uint32_t r0, r1, r2, r3;
                asm volatile("ldmatrix.sync.aligned.m8n8.x4.shared.b16 {%0,%1,%2,%3}, [%4];"
                    : "=r"(r0), "=r"(r1), "=r"(r2), "=r"(r3)
                    : "r"(bb + (nfp * 16 + brow) * ROWSTR + kbyte));
                b[nfp * 2 + 0][0] = r0; b[nfp * 2 + 0][1] = r2;
                b[nfp * 2 + 1][0] = r1; b[nfp * 2 + 1][1] = r3;
            }
            #pragma unroll
            for (int nf = 0; nf < 8; nf++)
                asm volatile(
                    "mma.sync.aligned.m16n8k16.row.col.f32.bf16.bf16.f32 "
                    "{%0,%1,%2,%3}, {%4,%5,%6,%7}, {%8,%9}, {%0,%1,%2,%3};"
                    : "+f"(acc[nf][0]), "+f"(acc[nf][1]), "+f"(acc[nf][2]), "+f"(acc[nf][3])
                    : "r"(a[0]), "r"(a[1]), "r"(a[2]), "r"(a[3]),
                      "r"(b[nf][0]), "r"(b[nf][1]));
        }
        __syncthreads();
    }
    const int gr = lane >> 2, gc = (lane & 3) * 2;
    #pragma unroll
    for (int nf = 0; nf < 8; nf++) {
        const int col = nf * 8 + gc;
        #pragma unroll
        for (int half = 0; half < 2; half++) {
            const int m = m0 + wid * 16 + gr + half * 8;
            float2 v = make_float2(-acc[nf][half * 2], -acc[nf][half * 2 + 1]);
            *(float2*)&dK[((size_t)bh * Nn + m) * QKd + col] = v;
        }
    }
}

// ============================================================================
// Repack dQ/dK [bh][n][qk] -> bf16 split planes [b*n][h*qk]
// ============================================================================
__global__ void __launch_bounds__(256) repack_split(
    const float* __restrict__ dQb, const float* __restrict__ dKb,
    bf16* __restrict__ q1, bf16* __restrict__ q2,
    bf16* __restrict__ k1, bf16* __restrict__ k2)
{
    int idx = blockIdx.x * 256 + threadIdx.x;
    int q = idx & 63;
    int h = (idx >> 6) & 15;
    int n = (idx >> 10) & 1023;
    int b = idx >> 20;
    size_t src = (((size_t)(b * Hh + h) * Nn) + n) * QKd + q;
    bf16 hh, ll;
    split2(dQb[src], hh, ll); q1[idx] = hh; q2[idx] = ll;
    split2(dKb[src], hh, ll); k1[idx] = hh; k2[idx] = ll;
}

// ============================================================================
// Final energy: E = -(1/BETA) * sum(lse) - 0.5 * sum(h^2). Deterministic.
// ============================================================================
__global__ void energy_final(const double* __restrict__ lse_part,
                             const double* __restrict__ h2_part,
                             float* __restrict__ out)
{
    __shared__ double sm[256];
    int t = threadIdx.x;
    double s = 0.0;
    for (int i = t; i < BH * (Nn / 16); i += 256) s += lse_part[i];
    double s2 = 0.0;
    for (int i = t; i < (BNr / 128) * (HIDd / 128); i += 256) s2 += h2_part[i];
    sm[t] = -8.0 * s - 0.5 * s2;
    __syncthreads();
    for (int o = 128; o > 0; o >>= 1) { if (t < o) sm[t] += sm[t + o]; __syncthreads(); }
    if (t == 0) out[(size_t)BNr * Dd] = (float)sm[0];
}

// ============================================================================
// Host launcher
// ============================================================================
extern "C" void kernel_launch(void* const* d_in, const int* in_sizes, int n_in,
                              void* d_out, int out_size)
{
    const float* x    = (const float*)d_in[0];
    const float* Wq   = (const float*)d_in[1];
    const float* Wk   = (const float*)d_in[2];
    const float* Whop = (const float*)d_in[3];
    float* out = (float*)d_out;

    float *pQ, *pK, *pdQ, *pdK, *pS;
    bf16 *pP;
    double *pLse, *pH2;
    bf16 *px1, *px2, *pwq1, *pwq2, *pwk1, *pwk2, *pwqt1, *pwqt2, *pwkt1, *pwkt2;
    bf16 *pwh1, *pwh2, *pwht1, *pwht2, *phb1, *phb2, *pdq1, *pdq2, *pdk1, *pdk2;
    bf16 *pq1, *pq2, *pk1, *pk2, *pqt, *pkt;

    cudaGetSymbolAddress((void**)&pQ,   g_Q);
    cudaGetSymbolAddress((void**)&pK,   g_K);
    cudaGetSymbolAddress((void**)&pdQ,  g_dQ);
    cudaGetSymbolAddress((void**)&pdK,  g_dK);
    cudaGetSymbolAddress((void**)&pS,   g_S);
    cudaGetSymbolAddress((void**)&pP,   g_P);
    cudaGetSymbolAddress((void**)&pLse, g_lse_part);
    cudaGetSymbolAddress((void**)&pH2,  g_h2_part);
    cudaGetSymbolAddress((void**)&px1,  g_x1);  cudaGetSymbolAddress((void**)&px2,  g_x2);
    cudaGetSymbolAddress((void**)&pwq1, g_wq1); cudaGetSymbolAddress((void**)&pwq2, g_wq2);
    cudaGetSymbolAddress((void**)&pwk1, g_wk1); cudaGetSymbolAddress((void**)&pwk2, g_wk2);
    cudaGetSymbolAddress((void**)&pwqt1,g_wqt1);cudaGetSymbolAddress((void**)&pwqt2,g_wqt2);
    cudaGetSymbolAddress((void**)&pwkt1,g_wkt1);cudaGetSymbolAddress((void**)&pwkt2,g_wkt2);
    cudaGetSymbolAddress((void**)&pwh1, g_wh1); cudaGetSymbolAddress((void**)&pwh2, g_wh2);
    cudaGetSymbolAddress((void**)&pwht1,g_wht1);cudaGetSymbolAddress((void**)&pwht2,g_wht2);
    cudaGetSymbolAddress((void**)&phb1, g_hb1); cudaGetSymbolAddress((void**)&phb2, g_hb2);
    cudaGetSymbolAddress((void**)&pdq1, g_dqm1);cudaGetSymbolAddress((void**)&pdq2, g_dqm2);
    cudaGetSymbolAddress((void**)&pdk1, g_dkm1);cudaGetSymbolAddress((void**)&pdk2, g_dkm2);
    cudaGetSymbolAddress((void**)&pq1,  g_q1);  cudaGetSymbolAddress((void**)&pq2,  g_q2);
    cudaGetSymbolAddress((void**)&pk1,  g_k1);  cudaGetSymbolAddress((void**)&pk2,  g_k2);
    cudaGetSymbolAddress((void**)&pqt,  g_qt);  cudaGetSymbolAddress((void**)&pkt,  g_kt);

    cudaFuncSetAttribute(tgemm<0>, cudaFuncAttributeMaxDynamicSharedMemorySize, TG_SMEM);
    cudaFuncSetAttribute(tgemm<1>, cudaFuncAttributeMaxDynamicSharedMemorySize, TG_SMEM);
    cudaFuncSetAttribute(tgemm<2>, cudaFuncAttributeMaxDynamicSharedMemorySize, TG_SMEM);
    cudaFuncSetAttribute(att_dq_h, cudaFuncAttributeMaxDynamicSharedMemorySize, 2 * DQ_STAGE);
    cudaFuncSetAttribute(att_dk_h, cudaFuncAttributeMaxDynamicSharedMemorySize, 2 * DK_STAGE);

    dim3 blk(256);

    // 0. bf16 splits of inputs
    split_plain<<<(BNr * Dd) / 256, blk>>>(x, px1, px2);
    split_plain<<<(HQ * Dd) / 256, blk>>>(Wq, pwq1, pwq2);
    split_plain<<<(HQ * Dd) / 256, blk>>>(Wk, pwk1, pwk2);
    split_plain<<<(Dd * HIDd) / 256, blk>>>(Whop, pwh1, pwh2);
    split_trans<<<(HQ * Dd) / 256, blk>>>(Wq, pwqt1, pwqt2, HQ, Dd);
    split_trans<<<(HQ * Dd) / 256, blk>>>(Wk, pwkt1, pwkt2, HQ, Dd);
    split_trans<<<(Dd * HIDd) / 256, blk>>>(Whop, pwht1, pwht2, Dd, HIDd);

    // 1-2. Q = X Wq^T, K = X Wk^T  (HMMA, scatter to [bh][n][qk] fp32)
    tgemm<1><<<dim3(HQ / 128, BNr / 128, 1), blk, TG_SMEM>>>(
        px1, px2, pwq1, pwq2, pQ, HQ, Dd, 1.f, 0, nullptr, nullptr, nullptr, 0, 0, 0);
    tgemm<1><<<dim3(HQ / 128, BNr / 128, 1), blk, TG_SMEM>>>(
        px1, px2, pwk1, pwk2, pK, HQ, Dd, 1.f, 0, nullptr, nullptr, nullptr, 0, 0, 0);

    // 3. attention operand prep: bf16 planes + transposes
    split_plain<<<(BH * Nn * QKd) / 256, blk>>>(pQ, pq1, pq2);
    split_plain<<<(BH * Nn * QKd) / 256, blk>>>(pK, pk1, pk2);
    trans_qk<<<dim3(Nn / 32, QKd / 32, BH), blk>>>(pQ, pK, pqt, pkt);

    // 4. S = BETA * Q K^T (batched HMMA split, fp32 out)
    tgemm<0><<<dim3(Nn / 128, Nn / 128, BH), blk, TG_SMEM>>>(
        pq1, pq2, pk1, pk2, pS, Nn, QKd, BETA, 0, nullptr, nullptr, nullptr,
        (size_t)Nn * QKd, (size_t)Nn * QKd, (size_t)Nn * Nn);

    // 5. softmax -> P' bf16 + lse partials
    att_convert3<<<dim3(Nn / 16, BH), blk>>>(pS, pP, pLse);

    // 6. dQ = -P' K,  dK = -P'^T Q  (HMMA)
    att_dq_h<<<dim3(Nn / 128, BH), blk, 2 * DQ_STAGE>>>(pP, pkt, pdQ);
    att_dk_h<<<dim3(Nn / 128, BH), blk, 2 * DK_STAGE>>>(pP, pqt, pdK);

    // 7. repack + split dQ/dK
    repack_split<<<(BNr * HQ) / 256, blk>>>(pdQ, pdK, pdq1, pdq2, pdk1, pdk2);

    // 8-9. grad = dQm @ Wq + dKm @ Wk
    tgemm<0><<<dim3(Dd / 128, BNr / 128, 1), blk, TG_SMEM>>>(
        pdq1, pdq2, pwqt1, pwqt2, out, Dd, HQ, 1.f, 0, nullptr, nullptr, nullptr, 0, 0, 0);
    tgemm<0><<<dim3(Dd / 128, BNr / 128, 1), blk, TG_SMEM>>>(
        pdk1, pdk2, pwkt1, pwkt2, out, Dd, HQ, 1.f, 1, nullptr, nullptr, nullptr, 0, 0, 0);

    // 10. Hb = relu(X @ W_hop); h2 partials
    tgemm<2><<<dim3(HIDd / 128, BNr / 128, 1), blk, TG_SMEM>>>(
        px1, px2, pwht1, pwht2, nullptr, HIDd, Dd, 1.f, 0, phb1, phb2, pH2, 0, 0, 0);

    // 11. grad -= Hb @ W_hop^T
    tgemm<0><<<dim3(Dd / 128, BNr / 128, 1), blk, TG_SMEM>>>(
        phb1, phb2, pwh1, pwh2, out, Dd, HIDd, -1.f, 1, nullptr, nullptr, nullptr, 0, 0, 0);

    // 12. energy scalar
    if (out_size > BNr * Dd)
        energy_final<<<1, 256>>>(pLse, pH2, out);
}

// round 10
// speedup vs baseline: 2.9047x; 1.2055x over previous
#include <cuda_runtime.h>
#include <cuda_bf16.h>
#include <math_constants.h>
#include <cstdint>

#define Bsz 4
#define Nn 1024
#define Dd 1024
#define Hh 16
#define QKd 64
#define HIDd 4096
#define BH 64           // B*H
#define BNr 4096        // B*N
#define HQ 1024         // H*QK
#define BETA 0.125f

typedef unsigned long long u64;
typedef __nv_bfloat16 bf16;

__device__ __forceinline__ uint32_t smem_u32(const void* p) {
    uint32_t a;
    asm("{ .reg .u64 t; cvta.to.shared.u64 t, %1; cvt.u32.u64 %0, t; }" : "=r"(a) : "l"(p));
    return a;
}
__device__ __forceinline__ void split2(float v, bf16& h, bf16& l) {
    h = __float2bfloat16(v);
    l = __float2bfloat16(v - __bfloat162float(h));
}
__device__ __forceinline__ uint32_t pack_bf2(float a, float b) {
    bf16 t[2] = {__float2bfloat16(a), __float2bfloat16(b)};
    return *(const uint32_t*)t;
}

// -------- device scratch (static allocation; no cudaMalloc anywhere) --------
__device__ bf16   g_Sb [(size_t)BH * Nn * Nn];    // beta*scores bf16 (128MB)
__device__ bf16   g_P  [(size_t)BH * Nn * Nn];    // softmax probs bf16 (128MB)
__device__ double g_lse_part[BH * (Nn / 16)];
__device__ double g_h2_part [(BNr / 128) * (HIDd / 128)];

__device__ bf16 g_x1 [(size_t)BNr * Dd],   g_x2 [(size_t)BNr * Dd];
__device__ bf16 g_wq1[(size_t)HQ * Dd],    g_wq2[(size_t)HQ * Dd];
__device__ bf16 g_wk1[(size_t)HQ * Dd],    g_wk2[(size_t)HQ * Dd];
__device__ bf16 g_wqt1[(size_t)Dd * HQ],   g_wqt2[(size_t)Dd * HQ];
__device__ bf16 g_wkt1[(size_t)Dd * HQ],   g_wkt2[(size_t)Dd * HQ];
__device__ bf16 g_wh1[(size_t)Dd * HIDd],  g_wh2[(size_t)Dd * HIDd];
__device__ bf16 g_wht1[(size_t)HIDd * Dd], g_wht2[(size_t)HIDd * Dd];
__device__ bf16 g_hb1[(size_t)BNr * HIDd], g_hb2[(size_t)BNr * HIDd];
__device__ bf16 g_dqm1[(size_t)BNr * HQ];
__device__ bf16 g_dkm1[(size_t)BNr * HQ];
// attention operands (single-plane bf16)
__device__ bf16 g_q1[(size_t)BH * Nn * QKd];
__device__ bf16 g_k1[(size_t)BH * Nn * QKd];
__device__ bf16 g_qt[(size_t)BH * QKd * Nn], g_kt[(size_t)BH * QKd * Nn];

// ============================================================================
// Split kernels: fp32 -> (hi, lo) bf16 planes
// ============================================================================
__global__ void __launch_bounds__(256) split_plain(
    const float* __restrict__ in, bf16* __restrict__ o1, bf16* __restrict__ o2)
{
    size_t i = (size_t)blockIdx.x * 256 + threadIdx.x;
    bf16 h, l; split2(in[i], h, l);
    o1[i] = h; o2[i] = l;
}
__global__ void __launch_bounds__(256) split_trans(
    const float* __restrict__ in, bf16* __restrict__ o1, bf16* __restrict__ o2,
    int R, int Ccols)
{
    size_t idx = (size_t)blockIdx.x * 256 + threadIdx.x;
    int r = (int)(idx % R);
    int c = (int)(idx / R);
    bf16 h, l; split2(in[(size_t)r * Ccols + c], h, l);
    o1[idx] = h; o2[idx] = l;
}

// ============================================================================
// Tiled transpose: q1,k1 bf16 [bh][n][qk] -> qt,kt bf16 [bh][qk][n]
// ============================================================================
__global__ void __launch_bounds__(256) trans_qk(
    const bf16* __restrict__ Q, const bf16* __restrict__ K,
    bf16* __restrict__ Qt, bf16* __restrict__ Kt)
{
    __shared__ bf16 tq[32][34], tk[32][34];
    const int n0 = blockIdx.x * 32, q0 = blockIdx.y * 32, bh = blockIdx.z;
    const bf16* Qb = Q + (size_t)bh * Nn * QKd;
    const bf16* Kb = K + (size_t)bh * Nn * QKd;
    const int tx = threadIdx.x & 31, ty = threadIdx.x >> 5;
    #pragma unroll
    for (int i = 0; i < 4; i++) {
        int n = ty + i * 8;
        tq[n][tx] = Qb[(size_t)(n0 + n) * QKd + q0 + tx];
        tk[n][tx] = Kb[(size_t)(n0 + n) * QKd + q0 + tx];
    }
    __syncthreads();
    #pragma unroll
    for (int i = 0; i < 4; i++) {
        int r = ty + i * 8;
        Qt[((size_t)bh * QKd + q0 + r) * Nn + n0 + tx] = tq[tx][r];
        Kt[((size_t)bh * QKd + q0 + r) * Nn + n0 + tx] = tk[tx][r];
    }
}

// ============================================================================
// HMMA GEMM, NS-sweep hi/lo split: C[m,n] = alpha * sum_k A[m,k]*B[n,k]
// Batched via blockIdx.z. EPI:
//   0: fp32 C (+)= alpha*D
//   1: bf16 scatter to [bh][n][qk] (O1)
//   2: relu; bf16-split to O1/O2; sum(v^2) partials
//   3: bf16 linear out O1 = bf16(alpha*D)
// ============================================================================
#define TILE_B 36864
#define ROWSTR 144
#define TG_SMEM (2 * TILE_B)

template<int EPI, int NS>
__global__ void __launch_bounds__(256) tgemm(
    const bf16* __restrict__ A1, const bf16* __restrict__ A2,
    const bf16* __restrict__ B1, const bf16* __restrict__ B2,
    float* __restrict__ C, int Ncols, int Kglob, float alpha, int accFlag,
    bf16* __restrict__ O1, bf16* __restrict__ O2, double* __restrict__ part,
    size_t zsA, size_t zsB, size_t zsC)
{
    extern __shared__ char dsm[];
    __shared__ double sred[256];
    const uint32_t sbase = smem_u32(dsm);

    const size_t zA = (size_t)blockIdx.z * zsA;
    const size_t zB = (size_t)blockIdx.z * zsB;
    A1 += zA; B1 += zB;
    if (NS == 3) { A2 += zA; B2 += zB; }
    if (EPI == 3) O1 += (size_t)blockIdx.z * zsC;
    else          C  += (size_t)blockIdx.z * zsC;

    const int t = threadIdx.x;
    const int wid = t >> 5, lane = t & 31;
    const int m0 = blockIdx.y * 128, n0 = blockIdx.x * 128;
    const int wm = wid >> 2, wn = wid & 3;

    const int KC = Kglob >> 6;
    const int TOT = NS * KC;

    float acc[4][4][4];
    #pragma unroll
    for (int i = 0; i < 4; i++)
        #pragma unroll
        for (int j = 0; j < 4; j++)
            #pragma unroll
            for (int r = 0; r < 4; r++) acc[i][j][r] = 0.f;

    const int lrow = t >> 3;
    const int lseg = (t & 7) * 8;

    auto issue_load = [&](int c) {
        const int p = (NS == 3) ? (c / KC) : 0;
        const int kb = c - p * KC;
        const bf16* Ap = (NS == 3 && p == 2) ? A2 : A1;
        const bf16* Bp = (NS == 3 && p == 1) ? B2 : B1;
        const uint32_t abase = sbase + (uint32_t)(c & 1) * TILE_B;
        const uint32_t bbase = abase + 18432;
        const size_t kEl = (size_t)(kb << 6) + lseg;
        #pragma unroll
        for (int i = 0; i < 4; i++) {
            const int row = lrow + i * 32;
            asm volatile("cp.async.cg.shared.global [%0], [%1], 16;"
                :: "r"(abase + row * ROWSTR + lseg * 2), "l"(Ap + (size_t)(m0 + row) * Kglob + kEl));
            asm volatile("cp.async.cg.shared.global [%0], [%1], 16;"
                :: "r"(bbase + row * ROWSTR + lseg * 2), "l"(Bp + (size_t)(n0 + row) * Kglob + kEl));
        }
        asm volatile("cp.async.commit_group;" ::: "memory");
    };

    issue_load(0);

    for (int c = 0; c < TOT; c++) {
        if (c + 1 < TOT) {
            issue_load(c + 1);
            asm volatile("cp.async.wait_group 1;" ::: "memory");
        } else {
            asm volatile("cp.async.wait_group 0;" ::: "memory");
        }
        __syncthreads();

        const uint32_t abase = sbase + (uint32_t)(c & 1) * TILE_B;
        const uint32_t bbase = abase + 18432;
        const int acol = ((lane >> 4) * 8) * 2;
        const int arow = (lane & 15);
        const int brow = (lane & 7) + ((lane >> 3) & 1) * 8;

        #pragma unroll
        for (int kk = 0; kk < 4; kk++) {
            const int kbyte = kk * 32 + acol;
            uint32_t a[4][4];
            #pragma unroll
            for (int mf = 0; mf < 4; mf++) {
                const uint32_t ad = abase + (wm * 64 + mf * 16 + arow) * ROWSTR + kbyte;
                asm volatile("ldmatrix.sync.aligned.m8n8.x4.shared.b16 {%0,%1,%2,%3}, [%4];"
                    : "=r"(a[mf][0]), "=r"(a[mf][1]), "=r"(a[mf][2]), "=r"(a[mf][3]) : "r"(ad));
            }
            uint32_t b[4][2];
            #pragma unroll
            for (int nfp = 0; nfp < 2; nfp++) {
                const uint32_t bd = bbase + (wn * 32 + nfp * 16 + brow) * ROWSTR + kbyte;
                uint32_t r0, r1, r2, r3;
                asm volatile("ldmatrix.sync.aligned.m8n8.x4.shared.b16 {%0,%1,%2,%3}, [%4];"
                    : "=r"(r0), "=r"(r1), "=r"(r2), "=r"(r3) : "r"(bd));
                b[nfp * 2 + 0][0] = r0; b[nfp * 2 + 0][1] = r2;
                b[nfp * 2 + 1][0] = r1; b[nfp * 2 + 1][1] = r3;
            }
            #pragma unroll
            for (int mf = 0; mf < 4; mf++)
                #pragma unroll
                for (int nf = 0; nf < 4; nf++)
                    asm volatile(
                        "mma.sync.aligned.m16n8k16.row.col.f32.bf16.bf16.f32 "
                        "{%0,%1,%2,%3}, {%4,%5,%6,%7}, {%8,%9}, {%0,%1,%2,%3};"
                        : "+f"(acc[mf][nf][0]), "+f"(acc[mf][nf][1]),
                          "+f"(acc[mf][nf][2]), "+f"(acc[mf][nf][3])
                        : "r"(a[mf][0]), "r"(a[mf][1]), "r"(a[mf][2]), "r"(a[mf][3]),
                          "r"(b[nf][0]), "r"(b[nf][1]));
        }
        __syncthreads();
    }

    const int gr = lane >> 2;
    const int gc = (lane & 3) * 2;
    float hs = 0.f;

    #pragma unroll
    for (int mf = 0; mf < 4; mf++) {
        #pragma unroll
        for (int nf = 0; nf < 4; nf++) {
            const int col = n0 + wn * 32 + nf * 8 + gc;
            #pragma unroll
            for (int half = 0; half < 2; half++) {
                const int row = m0 + wm * 64 + mf * 16 + gr + half * 8;
                const float va = acc[mf][nf][half * 2];
                const float vb = acc[mf][nf][half * 2 + 1];
                if (EPI == 1) {
                    const int h_ = col >> 6, q_ = col & 63;
                    const int b_ = row >> 10, n_ = row & 1023;
                    *(uint32_t*)&O1[(((size_t)(b_ * Hh + h_)) * Nn + n_) * QKd + q_] =
                        pack_bf2(va, vb);
                } else if (EPI == 2) {
                    const size_t off = (size_t)row * Ncols + col;
                    const float v0 = fmaxf(va, 0.f), v1 = fmaxf(vb, 0.f);
                    hs = fmaf(v0, v0, fmaf(v1, v1, hs));
                    bf16 h0, l0, h1, l1;
                    split2(v0, h0, l0); split2(v1, h1, l1);
                    bf16 hh[2] = {h0, h1}, ll[2] = {l0, l1};
                    *(uint32_t*)(O1 + off) = *(const uint32_t*)hh;
                    *(uint32_t*)(O2 + off) = *(const uint32_t*)ll;
                } else if (EPI == 3) {
                    const size_t off = (size_t)row * Ncols + col;
                    *(uint32_t*)&O1[off] = pack_bf2(va * alpha, vb * alpha);
                } else {
                    const size_t off = (size_t)row * Ncols + col;
                    float2 v = make_float2(va * alpha, vb * alpha);
                    if (accFlag) {
                        float2 o = *(const float2*)&C[off];
                        v.x += o.x; v.y += o.y;
                    }
                    *(float2*)&C[off] = v;
                }
            }
        }
    }
    if (EPI == 2) {
        sred[t] = (double)hs;
        __syncthreads();
        for (int o = 128; o > 0; o >>= 1) { if (t < o) sred[t] += sred[t + o]; __syncthreads(); }
        if (t == 0) part[blockIdx.y * gridDim.x + blockIdx.x] = sred[0];
    }
}

// ============================================================================
// Convert (1 DRAM read): P = softmax(S) row-wise, bf16 in/out; lse partials.
// grid (Nn/16, BH), 256 threads = 16 rows x 16 lanes; 64 els/lane in regs.
// ============================================================================
__global__ void __launch_bounds__(256) att_convert_b(
    const bf16* __restrict__ S, bf16* __restrict__ P, double* __restrict__ lse_part)
{
    const int bh = blockIdx.y;
    const int r0 = blockIdx.x * 16;
    const int t = threadIdx.x;
    const int rloc = t >> 4, lane = t & 15;
    const int row = r0 + rloc;
    const bf16* Sr = S + ((size_t)bh * Nn + row) * Nn;
    bf16* Pr = P + ((size_t)bh * Nn + row) * Nn;

    uint4 v[8];
    #pragma unroll
    for (int i = 0; i < 8; i++)
        v[i] = *(const uint4*)&Sr[(size_t)(i * 16 + lane) * 8];

    const __nv_bfloat162* hp = (const __nv_bfloat162*)v;
    float m = -CUDART_INF_F;
    #pragma unroll
    for (int j = 0; j < 32; j++) {
        float2 f = __bfloat1622float2(hp[j]);
        m = fmaxf(m, fmaxf(f.x, f.y));
    }
    #pragma unroll
    for (int o = 8; o > 0; o >>= 1) m = fmaxf(m, __shfl_xor_sync(0xffffffffu, m, o));

    float sum = 0.f;
    #pragma unroll
    for (int j = 0; j < 32; j++) {
        float2 f = __bfloat1622float2(hp[j]);
        sum += __expf(f.x - m) + __expf(f.y - m);
    }
    #pragma unroll
    for (int o = 8; o > 0; o >>= 1) sum += __shfl_xor_sync(0xffffffffu, sum, o);

    const float inv = 1.f / sum;
    #pragma unroll
    for (int i = 0; i < 8; i++) {
        uint4 w;
        bf16* wb = (bf16*)&w;
        const __nv_bfloat162* sp = (const __nv_bfloat162*)&v[i];
        #pragma unroll
        for (int j = 0; j < 4; j++) {
            float2 f = __bfloat1622float2(sp[j]);
            wb[2 * j + 0] = __float2bfloat16(__expf(f.x - m) * inv);
            wb[2 * j + 1] = __float2bfloat16(__expf(f.y - m) * inv);
        }
        *(uint4*)&Pr[(size_t)(i * 16 + lane) * 8] = w;
    }

    __shared__ double part[16];
    if (lane == 0) part[rloc] = (double)m + (double)logf(sum);
    __syncthreads();
    if (t == 0) {
        double s = 0.0;
        #pragma unroll
        for (int i = 0; i < 16; i++) s += part[i];
        lse_part[bh * (Nn / 16) + blockIdx.x] = s;
    }
}

// ============================================================================
// dQ-GEMM: dqm1[(b*N+n)][h*64+q] = bf16(-sum_m P'[n][m] * Kt[q][m])
// ============================================================================
#define DQ_STAGE 27648
__global__ void __launch_bounds__(256) att_dq_h(
    const bf16* __restrict__ P, const bf16* __restrict__ Kt, bf16* __restrict__ dqm)
{
    extern __shared__ char dsm[];
    const uint32_t sbase = smem_u32(dsm);
    const int t = threadIdx.x, wid = t >> 5, lane = t & 31;
    const int bh = blockIdx.y, n0 = blockIdx.x * 128;
    const bf16* Ag = P + (size_t)bh * Nn * Nn;
    const bf16* Bg = Kt + (size_t)bh * QKd * Nn;

    float acc[8][4];
    #pragma unroll
    for (int i = 0; i < 8; i++)
        #pragma unroll
        for (int r = 0; r < 4; r++) acc[i][r] = 0.f;

    const int lrow = t >> 3, lseg = (t & 7) * 8;

    auto load = [&](int kb) {
        const uint32_t ab = sbase + (uint32_t)(kb & 1) * DQ_STAGE;
        const uint32_t bb = ab + 18432;
        const size_t kEl = (size_t)(kb << 6) + lseg;
        #pragma unroll
        for (int i = 0; i < 4; i++) {
            const int row = lrow + i * 32;
            asm volatile("cp.async.cg.shared.global [%0], [%1], 16;"
                :: "r"(ab + row * ROWSTR + lseg * 2), "l"(Ag + (size_t)(n0 + row) * Nn + kEl));
        }
        #pragma unroll
        for (int i = 0; i < 2; i++) {
            const int row = lrow + i * 32;
            asm volatile("cp.async.cg.shared.global [%0], [%1], 16;"
                :: "r"(bb + row * ROWSTR + lseg * 2), "l"(Bg + (size_t)row * Nn + kEl));
        }
        asm volatile("cp.async.commit_group;" ::: "memory");
    };

    load(0);
    for (int kb = 0; kb < 16; kb++) {
        if (kb < 15) { load(kb + 1); asm volatile("cp.async.wait_group 1;" ::: "memory"); }
        else         { asm volatile("cp.async.wait_group 0;" ::: "memory"); }
        __syncthreads();
        const uint32_t ab = sbase + (uint32_t)(kb & 1) * DQ_STAGE;
        const uint32_t bb = ab + 18432;
        const int acol = ((lane >> 4) * 8) * 2;
        const int arow = lane & 15;
        const int brow = (lane & 7) + ((lane >> 3) & 1) * 8;
        #pragma unroll
        for (int kk = 0; kk < 4; kk++) {
            const int kbyte = kk * 32 + acol;
            uint32_t a[4];
            asm volatile("ldmatrix.sync.aligned.m8n8.x4.shared.b16 {%0,%1,%2,%3}, [%4];"
                : "=r"(a[0]), "=r"(a[1]), "=r"(a[2]), "=r"(a[3])
                : "r"(ab + (wid * 16 + arow) * ROWSTR + kbyte));
            uint32_t b[8][2];
            #pragma unroll
            for (int nfp = 0; nfp < 4; nfp++) {
                uint32_t r0, r1, r2, r3;
                asm volatile("ldmatrix.sync.aligned.m8n8.x4.shared.b16 {%0,%1,%2,%3}, [%4];"
                    : "=r"(r0), "=r"(r1), "=r"(r2), "=r"(r3)
                    : "r"(bb + (nfp * 16 + brow) * ROWSTR + kbyte));
                b[nfp * 2 + 0][0] = r0; b[nfp * 2 + 0][1] = r2;
                b[nfp * 2 + 1][0] = r1; b[nfp * 2 + 1][1] = r3;
            }
            #pragma unroll
            for (int nf = 0; nf < 8; nf++)
                asm volatile(
                    "mma.sync.aligned.m16n8k16.row.col.f32.bf16.bf16.f32 "
                    "{%0,%1,%2,%3}, {%4,%5,%6,%7}, {%8,%9}, {%0,%1,%2,%3};"
                    : "+f"(acc[nf][0]), "+f"(acc[nf][1]), "+f"(acc[nf][2]), "+f"(acc[nf][3])
                    : "r"(a[0]), "r"(a[1]), "r"(a[2]), "r"(a[3]),
                      "r"(b[nf][0]), "r"(b[nf][1]));
        }
        __syncthreads();
    }
    const int gr = lane >> 2, gc = (lane & 3) * 2;
    const int b_ = bh >> 4, h_ = bh & 15;
    #pragma unroll
    for (int nf = 0; nf < 8; nf++) {
        const int col = nf * 8 + gc;
        #pragma unroll
        for (int half = 0; half < 2; half++) {
            const int n = n0 + wid * 16 + gr + half * 8;
            *(uint32_t*)&dqm[((size_t)(b_ * 1024 + n)) * 1024 + h_ * 64 + col] =
                pack_bf2(-acc[nf][half * 2], -acc[nf][half * 2 + 1]);
        }
    }
}

// ============================================================================
// dK-GEMM: dkm1[(b*N+m)][h*64+q] = bf16(-sum_n P'[n][m] * Qt[q][n])
// ============================================================================
#define DK_ASTR 272
#define DK_STAGE 26624
__global__ void __launch_bounds__(256) att_dk_h(
    const bf16* __restrict__ P, const bf16* __restrict__ Qt, bf16* __restrict__ dkm)
{
    extern __shared__ char dsm[];
    const uint32_t sbase = smem_u32(dsm);
    const int t = threadIdx.x, wid = t >> 5, lane = t & 31;
    const int bh = blockIdx.y, m0 = blockIdx.x * 128;
    const bf16* Ag = P + (size_t)bh * Nn * Nn;
    const bf16* Bg = Qt + (size_t)bh * QKd * Nn;

    float acc[8][4];
    #pragma unroll
    for (int i = 0; i < 8; i++)
        #pragma unroll
        for (int r = 0; r < 4; r++) acc[i][r] = 0.f;

    auto load = [&](int kb) {
        const uint32_t ab = sbase + (uint32_t)(kb & 1) * DK_STAGE;
        const uint32_t bb = ab + 17408;
        const int ar = t >> 4, aseg = (t & 15) * 8;
        #pragma unroll
        for (int i = 0; i < 4; i++) {
            const int row = ar + i * 16;
            asm volatile("cp.async.cg.shared.global [%0], [%1], 16;"
                :: "r"(ab + row * DK_ASTR + aseg * 2),
                   "l"(Ag + (size_t)((kb << 6) + row) * Nn + m0 + aseg));
        }
        const int br = t >> 3, bseg = (t & 7) * 8;
        #pragma unroll
        for (int i = 0; i < 2; i++) {
            const int row = br + i * 32;
            asm volatile("cp.async.cg.shared.global [%0], [%1], 16;"
                :: "r"(bb + row * ROWSTR + bseg * 2),
                   "l"(Bg + (size_t)row * Nn + (kb << 6) + bseg));
        }
        asm volatile("cp.async.commit_group;" ::: "memory");
    };

    load(0);
    for (int kb = 0; kb < 16; kb++) {
        if (kb < 15) { load(kb + 1); asm volatile("cp.async.wait_group 1;" ::: "memory"); }
        else         { asm volatile("cp.async.wait_group 0;" ::: "memory"); }
        __syncthreads();
        const uint32_t ab = sbase + (uint32_t)(kb & 1) * DK_STAGE;
        const uint32_t bb = ab + 17408;
        const int tl = lane >> 3;
        const int brow = (lane & 7) + ((lane >> 3) & 1) * 8;
        const int bcol = ((lane >> 4) * 8) * 2;
        #pragma unroll
        for (int kk = 0; kk < 4; kk++) {
            uint32_t a[4];
            const uint32_t ad = ab + (kk * 16 + (tl >> 1) * 8 + (lane & 7)) * DK_ASTR
                              + (wid * 16 + (tl & 1) * 8) * 2;
            asm volatile("ldmatrix.sync.aligned.m8n8.x4.trans.shared.b16 {%0,%1,%2,%3}, [%4];"
                : "=r"(a[0]), "=r"(a[1]), "=r"(a[2]), "=r"(a[3]) : "r"(ad));
            uint32_t b[8][2];
            const int kbyte = kk * 32 + bcol;
            #pragma unroll
            for (int nfp = 0; nfp < 4; nfp++) {
                uint32_t r0, r1, r2, r3;
                asm volatile("ldmatrix.sync.aligned.m8n8.x4.shared.b16 {%0,%1,%2,%3}, [%4];"
                    : "=r"(r0), "=r"(r1), "=r"(r2), "=r"(r3)
                    : "r"(bb + (nfp * 16 + brow) * ROWSTR + kbyte));
                b[nfp * 2 + 0][0] = r0; b[nfp * 2 + 0][1] = r2;
                b[nfp * 2 + 1][0] = r1; b[nfp * 2 + 1][1] = r3;
            }
            #pragma unroll
            for (int nf = 0; nf < 8; nf++)
                asm volatile(
                    "mma.sync.aligned.m16n8k16.row.col.f32.bf16.bf16.f32 "
                    "{%0,%1,%2,%3}, {%4,%5,%6,%7}, {%8,%9}, {%0,%1,%2,%3};"
                    : "+f"(acc[nf][0]), "+f"(acc[nf][1]), "+f"(acc[nf][2]), "+f"(acc[nf][3])
                    : "r"(a[0]), "r"(a[1]), "r"(a[2]), "r"(a[3]),
                      "r"(b[nf][0]), "r"(b[nf][1]));
        }
        __syncthreads();
    }
    const int gr = lane >> 2, gc = (lane & 3) * 2;
    const int b_ = bh >> 4, h_ = bh & 15;
    #pragma unroll
    for (int nf = 0; nf < 8; nf++) {
        const int col = nf * 8 + gc;
        #pragma unroll
        for (int half = 0; half < 2; half++) {
            const int m = m0 + wid * 16 + gr + half * 8;
            *(uint32_t*)&dkm[((size_t)(b_ * 1024 + m)) * 1024 + h_ * 64 + col] =
                pack_bf2(-acc[nf][half * 2], -acc[nf][half * 2 + 1]);
        }
    }
}

// ============================================================================
// Final energy: E = -(1/BETA) * sum(lse) - 0.5 * sum(h^2). Deterministic.
// ============================================================================
__global__ void energy_final(const double* __restrict__ lse_part,
                             const double* __restrict__ h2_part,
                             float* __restrict__ out)
{
    __shared__ double sm[256];
    int t = threadIdx.x;
    double s = 0.0;
    for (int i = t; i < BH * (Nn / 16); i += 256) s += lse_part[i];
    double s2 = 0.0;
    for (int i = t; i < (BNr / 128) * (HIDd / 128); i += 256) s2 += h2_part[i];
    sm[t] = -8.0 * s - 0.5 * s2;
    __syncthreads();
    for (int o = 128; o > 0; o >>= 1) { if (t < o) sm[t] += sm[t + o]; __syncthreads(); }
    if (t == 0) out[(size_t)BNr * Dd] = (float)sm[0];
}

// ============================================================================
// Host launcher
// ============================================================================
extern "C" void kernel_launch(void* const* d_in, const int* in_sizes, int n_in,
                              void* d_out, int out_size)
{
    const float* x    = (const float*)d_in[0];
    const float* Wq   = (const float*)d_in[1];
    const float* Wk   = (const float*)d_in[2];
    const float* Whop = (const float*)d_in[3];
    float* out = (float*)d_out;

    bf16 *pSb, *pP;
    double *pLse, *pH2;
    bf16 *px1, *px2, *pwq1, *pwq2, *pwk1, *pwk2, *pwqt1, *pwqt2, *pwkt1, *pwkt2;
    bf16 *pwh1, *pwh2, *pwht1, *pwht2, *phb1, *phb2, *pdq1, *pdk1;
    bf16 *pq1, *pk1, *pqt, *pkt;

    cudaGetSymbolAddress((void**)&pSb,  g_Sb);
    cudaGetSymbolAddress((void**)&pP,   g_P);
    cudaGetSymbolAddress((void**)&pLse, g_lse_part);
    cudaGetSymbolAddress((void**)&pH2,  g_h2_part);
    cudaGetSymbolAddress((void**)&px1,  g_x1);  cudaGetSymbolAddress((void**)&px2,  g_x2);
    cudaGetSymbolAddress((void**)&pwq1, g_wq1); cudaGetSymbolAddress((void**)&pwq2, g_wq2);
    cudaGetSymbolAddress((void**)&pwk1, g_wk1); cudaGetSymbolAddress((void**)&pwk2, g_wk2);
    cudaGetSymbolAddress((void**)&pwqt1,g_wqt1);cudaGetSymbolAddress((void**)&pwqt2,g_wqt2);
    cudaGetSymbolAddress((void**)&pwkt1,g_wkt1);cudaGetSymbolAddress((void**)&pwkt2,g_wkt2);
    cudaGetSymbolAddress((void**)&pwh1, g_wh1); cudaGetSymbolAddress((void**)&pwh2, g_wh2);
    cudaGetSymbolAddress((void**)&pwht1,g_wht1);cudaGetSymbolAddress((void**)&pwht2,g_wht2);
    cudaGetSymbolAddress((void**)&phb1, g_hb1); cudaGetSymbolAddress((void**)&phb2, g_hb2);
    cudaGetSymbolAddress((void**)&pdq1, g_dqm1);
    cudaGetSymbolAddress((void**)&pdk1, g_dkm1);
    cudaGetSymbolAddress((void**)&pq1,  g_q1);
    cudaGetSymbolAddress((void**)&pk1,  g_k1);
    cudaGetSymbolAddress((void**)&pqt,  g_qt);  cudaGetSymbolAddress((void**)&pkt,  g_kt);

    cudaFuncSetAttribute(tgemm<0,1>, cudaFuncAttributeMaxDynamicSharedMemorySize, TG_SMEM);
    cudaFuncSetAttribute(tgemm<0,3>, cudaFuncAttributeMaxDynamicSharedMemorySize, TG_SMEM);
    cudaFuncSetAttribute(tgemm<1,3>, cudaFuncAttributeMaxDynamicSharedMemorySize, TG_SMEM);
    cudaFuncSetAttribute(tgemm<2,3>, cudaFuncAttributeMaxDynamicSharedMemorySize, TG_SMEM);
    cudaFuncSetAttribute(tgemm<3,1>, cudaFuncAttributeMaxDynamicSharedMemorySize, TG_SMEM);
    cudaFuncSetAttribute(att_dq_h, cudaFuncAttributeMaxDynamicSharedMemorySize, 2 * DQ_STAGE);
    cudaFuncSetAttribute(att_dk_h, cudaFuncAttributeMaxDynamicSharedMemorySize, 2 * DK_STAGE);

    dim3 blk(256);

    // 0. bf16 splits of inputs
    split_plain<<<(BNr * Dd) / 256, blk>>>(x, px1, px2);
    split_plain<<<(HQ * Dd) / 256, blk>>>(Wq, pwq1, pwq2);
    split_plain<<<(HQ * Dd) / 256, blk>>>(Wk, pwk1, pwk2);
    split_plain<<<(Dd * HIDd) / 256, blk>>>(Whop, pwh1, pwh2);
    split_trans<<<(HQ * Dd) / 256, blk>>>(Wq, pwqt1, pwqt2, HQ, Dd);
    split_trans<<<(HQ * Dd) / 256, blk>>>(Wk, pwkt1, pwkt2, HQ, Dd);
    split_trans<<<(Dd * HIDd) / 256, blk>>>(Whop, pwht1, pwht2, Dd, HIDd);

    // 1-2. Q,K projections (3-sweep HMMA) -> bf16 q1/k1 scattered [bh][n][qk]
    tgemm<1,3><<<dim3(HQ / 128, BNr / 128, 1), blk, TG_SMEM>>>(
        px1, px2, pwq1, pwq2, nullptr, HQ, Dd, 1.f, 0, pq1, nullptr, nullptr, 0, 0, 0);
    tgemm<1,3><<<dim3(HQ / 128, BNr / 128, 1), blk, TG_SMEM>>>(
        px1, px2, pwk1, pwk2, nullptr, HQ, Dd, 1.f, 0, pk1, nullptr, nullptr, 0, 0, 0);

    // 3. transposes for dq/dk B-operands
    trans_qk<<<dim3(Nn / 32, QKd / 32, BH), blk>>>(pq1, pk1, pqt, pkt);

    // 4. S = BETA * Q K^T (single-sweep batched HMMA, bf16 out)
    tgemm<3,1><<<dim3(Nn / 128, Nn / 128, BH), blk, TG_SMEM>>>(
        pq1, nullptr, pk1, nullptr, nullptr, Nn, QKd, BETA, 0, pSb, nullptr, nullptr,
        (size_t)Nn * QKd, (size_t)Nn * QKd, (size_t)Nn * Nn);

    // 5. softmax -> P bf16 + lse partials (single DRAM read)
    att_convert_b<<<dim3(Nn / 16, BH), blk>>>(pSb, pP, pLse);

    // 6. dQm = -P K, dKm = -P^T Q  -> bf16 [b*n][h*qk] directly
    att_dq_h<<<dim3(Nn / 128, BH), blk, 2 * DQ_STAGE>>>(pP, pkt, pdq1);
    att_dk_h<<<dim3(Nn / 128, BH), blk, 2 * DK_STAGE>>>(pP, pqt, pdk1);

    // 7-8. grad = dQm @ Wq + dKm @ Wk  (single-sweep)
    tgemm<0,1><<<dim3(Dd / 128, BNr / 128, 1), blk, TG_SMEM>>>(
        pdq1, nullptr, pwqt1, nullptr, out, Dd, HQ, 1.f, 0, nullptr, nullptr, nullptr, 0, 0, 0);
    tgemm<0,1><<<dim3(Dd / 128, BNr / 128, 1), blk, TG_SMEM>>>(
        pdk1, nullptr, pwkt1, nullptr, out, Dd, HQ, 1.f, 1, nullptr, nullptr, nullptr, 0, 0, 0);

    // 9. Hb = relu(X @ W_hop) (3-sweep); h2 partials
    tgemm<2,3><<<dim3(HIDd / 128, BNr / 128, 1), blk, TG_SMEM>>>(
        px1, px2, pwht1, pwht2, nullptr, HIDd, Dd, 1.f, 0, phb1, phb2, pH2, 0, 0, 0);

    // 10. grad -= Hb @ W_hop^T (3-sweep)
    tgemm<0,3><<<dim3(Dd / 128, BNr / 128, 1), blk, TG_SMEM>>>(
        phb1, phb2, pwh1, pwh2, out, Dd, HIDd, -1.f, 1, nullptr, nullptr, nullptr, 0, 0, 0);

    // 11. energy scalar
    if (out_size > BNr * Dd)
        energy_final<<<1, 256>>>(pLse, pH2, out);
}

// round 11
// speedup vs baseline: 3.3400x; 1.1499x over previous
#include <cuda_runtime.h>
#include <cuda_bf16.h>
#include <math_constants.h>
#include <cstdint>

#define Bsz 4
#define Nn 1024
#define Dd 1024
#define Hh 16
#define QKd 64
#define HIDd 4096
#define BH 64           // B*H
#define BNr 4096        // B*N
#define HQ 1024         // H*QK
#define BETA 0.125f

typedef unsigned long long u64;
typedef __nv_bfloat16 bf16;

__device__ __forceinline__ uint32_t smem_u32(const void* p) {
    uint32_t a;
    asm("{ .reg .u64 t; cvta.to.shared.u64 t, %1; cvt.u32.u64 %0, t; }" : "=r"(a) : "l"(p));
    return a;
}
__device__ __forceinline__ void split2(float v, bf16& h, bf16& l) {
    h = __float2bfloat16(v);
    l = __float2bfloat16(v - __bfloat162float(h));
}
__device__ __forceinline__ uint32_t pack_bf2(float a, float b) {
    bf16 t[2] = {__float2bfloat16(a), __float2bfloat16(b)};
    return *(const uint32_t*)t;
}

// -------- device scratch (static allocation; no cudaMalloc anywhere) --------
__device__ bf16   g_Sb [(size_t)BH * Nn * Nn];    // beta*scores bf16 (128MB)
__device__ bf16   g_P  [(size_t)BH * Nn * Nn];    // softmax probs bf16 (128MB)
__device__ double g_lse_part[BH * (Nn / 16)];
__device__ double g_h2_part [(BNr / 128) * (HIDd / 128)];

__device__ bf16 g_x1 [(size_t)BNr * Dd],   g_x2 [(size_t)BNr * Dd];
__device__ bf16 g_wq1[(size_t)HQ * Dd];                    // hi only (1-sweep proj)
__device__ bf16 g_wk1[(size_t)HQ * Dd];
__device__ bf16 g_wt [(size_t)Dd * 2048];                  // [d][ WqT | WkT ]
__device__ bf16 g_wh1[(size_t)Dd * HIDd],  g_wh2[(size_t)Dd * HIDd];
__device__ bf16 g_wht1[(size_t)HIDd * Dd], g_wht2[(size_t)HIDd * Dd];
__device__ bf16 g_hb1[(size_t)BNr * HIDd], g_hb2[(size_t)BNr * HIDd];
__device__ bf16 g_dm [(size_t)BNr * 2048];                 // [b*n][ dqm | dkm ]
__device__ bf16 g_q1[(size_t)BH * Nn * QKd];
__device__ bf16 g_k1[(size_t)BH * Nn * QKd];
__device__ bf16 g_qt[(size_t)BH * QKd * Nn], g_kt[(size_t)BH * QKd * Nn];

// ============================================================================
// Vectorized fp32 -> bf16 converters (4 els/thread)
// ============================================================================
__global__ void __launch_bounds__(256) split_plain4(
    const float* __restrict__ in, bf16* __restrict__ o1, bf16* __restrict__ o2)
{
    size_t i = ((size_t)blockIdx.x * 256 + threadIdx.x) * 4;
    float4 v = *(const float4*)(in + i);
    bf16 h[4], l[4];
    split2(v.x, h[0], l[0]); split2(v.y, h[1], l[1]);
    split2(v.z, h[2], l[2]); split2(v.w, h[3], l[3]);
    *(u64*)(o1 + i) = *(const u64*)h;
    *(u64*)(o2 + i) = *(const u64*)l;
}
__global__ void __launch_bounds__(256) cvt_plain4(
    const float* __restrict__ in, bf16* __restrict__ o1)
{
    size_t i = ((size_t)blockIdx.x * 256 + threadIdx.x) * 4;
    float4 v = *(const float4*)(in + i);
    bf16 h[4] = {__float2bfloat16(v.x), __float2bfloat16(v.y),
                 __float2bfloat16(v.z), __float2bfloat16(v.w)};
    *(u64*)(o1 + i) = *(const u64*)h;
}

// ============================================================================
// Tiled transposes (coalesced both sides), fp32 in -> bf16 out[c][r]
// ============================================================================
__global__ void __launch_bounds__(256) trans_cvt1(
    const float* __restrict__ in, bf16* __restrict__ out, int R, int C, int OS)
{
    __shared__ float tile[32][33];
    const int c0 = blockIdx.x * 32, r0 = blockIdx.y * 32;
    const int tx = threadIdx.x & 31, ty = threadIdx.x >> 5;
    #pragma unroll
    for (int i = 0; i < 4; i++)
        tile[ty + i * 8][tx] = in[(size_t)(r0 + ty + i * 8) * C + c0 + tx];
    __syncthreads();
    #pragma unroll
    for (int i = 0; i < 4; i++)
        out[(size_t)(c0 + ty + i * 8) * OS + r0 + tx] = __float2bfloat16(tile[tx][ty + i * 8]);
}
__global__ void __launch_bounds__(256) trans_split(
    const float* __restrict__ in, bf16* __restrict__ o1, bf16* __restrict__ o2,
    int R, int C, int OS)
{
    __shared__ float tile[32][33];
    const int c0 = blockIdx.x * 32, r0 = blockIdx.y * 32;
    const int tx = threadIdx.x & 31, ty = threadIdx.x >> 5;
    #pragma unroll
    for (int i = 0; i < 4; i++)
        tile[ty + i * 8][tx] = in[(size_t)(r0 + ty + i * 8) * C + c0 + tx];
    __syncthreads();
    #pragma unroll
    for (int i = 0; i < 4; i++) {
        bf16 h, l; split2(tile[tx][ty + i * 8], h, l);
        size_t off = (size_t)(c0 + ty + i * 8) * OS + r0 + tx;
        o1[off] = h; o2[off] = l;
    }
}

// ============================================================================
// Tiled transpose: q1,k1 bf16 [bh][n][qk] -> qt,kt bf16 [bh][qk][n]
// ============================================================================
__global__ void __launch_bounds__(256) trans_qk(
    const bf16* __restrict__ Q, const bf16* __restrict__ K,
    bf16* __restrict__ Qt, bf16* __restrict__ Kt)
{
    __shared__ bf16 tq[32][34], tk[32][34];
    const int n0 = blockIdx.x * 32, q0 = blockIdx.y * 32, bh = blockIdx.z;
    const bf16* Qb = Q + (size_t)bh * Nn * QKd;
    const bf16* Kb = K + (size_t)bh * Nn * QKd;
    const int tx = threadIdx.x & 31, ty = threadIdx.x >> 5;
    #pragma unroll
    for (int i = 0; i < 4; i++) {
        int n = ty + i * 8;
        tq[n][tx] = Qb[(size_t)(n0 + n) * QKd + q0 + tx];
        tk[n][tx] = Kb[(size_t)(n0 + n) * QKd + q0 + tx];
    }
    __syncthreads();
    #pragma unroll
    for (int i = 0; i < 4; i++) {
        int r = ty + i * 8;
        Qt[((size_t)bh * QKd + q0 + r) * Nn + n0 + tx] = tq[tx][r];
        Kt[((size_t)bh * QKd + q0 + r) * Nn + n0 + tx] = tk[tx][r];
    }
}

// ============================================================================
// HMMA GEMM, NS-sweep hi/lo split: C[m,n] = alpha * sum_k A[m,k]*B[n,k]
// Batched via blockIdx.z. EPI:
//   0: fp32 C (+)= alpha*D
//   1: bf16 scatter to [bh][n][qk] (O1)
//   2: relu; bf16-split to O1/O2; sum(v^2) partials
//   3: bf16 linear out O1 = bf16(alpha*D)
// ============================================================================
#define TILE_B 36864
#define ROWSTR 144
#define TG_SMEM (2 * TILE_B)

template<int EPI, int NS>
__global__ void __launch_bounds__(256) tgemm(
    const bf16* __restrict__ A1, const bf16* __restrict__ A2,
    const bf16* __restrict__ B1, const bf16* __restrict__ B2,
    float* __restrict__ C, int Ncols, int Kglob, float alpha, int accFlag,
    bf16* __restrict__ O1, bf16* __restrict__ O2, double* __restrict__ part,
    size_t zsA, size_t zsB, size_t zsC)
{
    extern __shared__ char dsm[];
    __shared__ double sred[256];
    const uint32_t sbase = smem_u32(dsm);

    const size_t zA = (size_t)blockIdx.z * zsA;
    const size_t zB = (size_t)blockIdx.z * zsB;
    A1 += zA; B1 += zB;
    if (NS == 3) { A2 += zA; B2 += zB; }
    if (EPI == 3) O1 += (size_t)blockIdx.z * zsC;
    else          C  += (size_t)blockIdx.z * zsC;

    const int t = threadIdx.x;
    const int wid = t >> 5, lane = t & 31;
    const int m0 = blockIdx.y * 128, n0 = blockIdx.x * 128;
    const int wm = wid >> 2, wn = wid & 3;

    const int KC = Kglob >> 6;
    const int TOT = NS * KC;

    float acc[4][4][4];
    #pragma unroll
    for (int i = 0; i < 4; i++)
        #pragma unroll
        for (int j = 0; j < 4; j++)
            #pragma unroll
            for (int r = 0; r < 4; r++) acc[i][j][r] = 0.f;

    const int lrow = t >> 3;
    const int lseg = (t & 7) * 8;

    auto issue_load = [&](int c) {
        const int p = (NS == 3) ? (c / KC) : 0;
        const int kb = c - p * KC;
        const bf16* Ap = (NS == 3 && p == 2) ? A2 : A1;
        const bf16* Bp = (NS == 3 && p == 1) ? B2 : B1;
        const uint32_t abase = sbase + (uint32_t)(c & 1) * TILE_B;
        const uint32_t bbase = abase + 18432;
        const size_t kEl = (size_t)(kb << 6) + lseg;
        #pragma unroll
        for (int i = 0; i < 4; i++) {
            const int row = lrow + i * 32;
            asm volatile("cp.async.cg.shared.global [%0], [%1], 16;"
                :: "r"(abase + row * ROWSTR + lseg * 2), "l"(Ap + (size_t)(m0 + row) * Kglob + kEl));
            asm volatile("cp.async.cg.shared.global [%0], [%1], 16;"
                :: "r"(bbase + row * ROWSTR + lseg * 2), "l"(Bp + (size_t)(n0 + row) * Kglob + kEl));
        }
        asm volatile("cp.async.commit_group;" ::: "memory");
    };

    issue_load(0);

    for (int c = 0; c < TOT; c++) {
        if (c + 1 < TOT) {
            issue_load(c + 1);
            asm volatile("cp.async.wait_group 1;" ::: "memory");
        } else {
            asm volatile("cp.async.wait_group 0;" ::: "memory");
        }
        __syncthreads();

        const uint32_t abase = sbase + (uint32_t)(c & 1) * TILE_B;
        const uint32_t bbase = abase + 18432;
        const int acol = ((lane >> 4) * 8) * 2;
        const int arow = (lane & 15);
        const int brow = (lane & 7) + ((lane >> 3) & 1) * 8;

        #pragma unroll
        for (int kk = 0; kk < 4; kk++) {
            const int kbyte = kk * 32 + acol;
            uint32_t a[4][4];
            #pragma unroll
            for (int mf = 0; mf < 4; mf++) {
                const uint32_t ad = abase + (wm * 64 + mf * 16 + arow) * ROWSTR + kbyte;
                asm volatile("ldmatrix.sync.aligned.m8n8.x4.shared.b16 {%0,%1,%2,%3}, [%4];"
                    : "=r"(a[mf][0]), "=r"(a[mf][1]), "=r"(a[mf][2]), "=r"(a[mf][3]) : "r"(ad));
            }
            uint32_t b[4][2];
            #pragma unroll
            for (int nfp = 0; nfp < 2; nfp++) {
                const uint32_t bd = bbase + (wn * 32 + nfp * 16 + brow) * ROWSTR + kbyte;
                uint32_t r0, r1, r2, r3;
                asm volatile("ldmatrix.sync.aligned.m8n8.x4.shared.b16 {%0,%1,%2,%3}, [%4];"
                    : "=r"(r0), "=r"(r1), "=r"(r2), "=r"(r3) : "r"(bd));
                b[nfp * 2 + 0][0] = r0; b[nfp * 2 + 0][1] = r2;
                b[nfp * 2 + 1][0] = r1; b[nfp * 2 + 1][1] = r3;
            }
            #pragma unroll
            for (int mf = 0; mf < 4; mf++)
                #pragma unroll
                for (int nf = 0; nf < 4; nf++)
                    asm volatile(
                        "mma.sync.aligned.m16n8k16.row.col.f32.bf16.bf16.f32 "
                        "{%0,%1,%2,%3}, {%4,%5,%6,%7}, {%8,%9}, {%0,%1,%2,%3};"
                        : "+f"(acc[mf][nf][0]), "+f"(acc[mf][nf][1]),
                          "+f"(acc[mf][nf][2]), "+f"(acc[mf][nf][3])
                        : "r"(a[mf][0]), "r"(a[mf][1]), "r"(a[mf][2]), "r"(a[mf][3]),
                          "r"(b[nf][0]), "r"(b[nf][1]));
        }
        __syncthreads();
    }

    const int gr = lane >> 2;
    const int gc = (lane & 3) * 2;
    float hs = 0.f;

    #pragma unroll
    for (int mf = 0; mf < 4; mf++) {
        #pragma unroll
        for (int nf = 0; nf < 4; nf++) {
            const int col = n0 + wn * 32 + nf * 8 + gc;
            #pragma unroll
            for (int half = 0; half < 2; half++) {
                const int row = m0 + wm * 64 + mf * 16 + gr + half * 8;
                const float va = acc[mf][nf][half * 2];
                const float vb = acc[mf][nf][half * 2 + 1];
                if (EPI == 1) {
                    const int h_ = col >> 6, q_ = col & 63;
                    const int b_ = row >> 10, n_ = row & 1023;
                    *(uint32_t*)&O1[(((size_t)(b_ * Hh + h_)) * Nn + n_) * QKd + q_] =
                        pack_bf2(va, vb);
                } else if (EPI == 2) {
                    const size_t off = (size_t)row * Ncols + col;
                    const float v0 = fmaxf(va, 0.f), v1 = fmaxf(vb, 0.f);
                    hs = fmaf(v0, v0, fmaf(v1, v1, hs));
                    bf16 h0, l0, h1, l1;
                    split2(v0, h0, l0); split2(v1, h1, l1);
                    bf16 hh[2] = {h0, h1}, ll[2] = {l0, l1};
                    *(uint32_t*)(O1 + off) = *(const uint32_t*)hh;
                    *(uint32_t*)(O2 + off) = *(const uint32_t*)ll;
                } else if (EPI == 3) {
                    const size_t off = (size_t)row * Ncols + col;
                    *(uint32_t*)&O1[off] = pack_bf2(va * alpha, vb * alpha);
                } else {
                    const size_t off = (size_t)row * Ncols + col;
                    float2 v = make_float2(va * alpha, vb * alpha);
                    if (accFlag) {
                        float2 o = *(const float2*)&C[off];
                        v.x += o.x; v.y += o.y;
                    }
                    *(float2*)&C[off] = v;
                }
            }
        }
    }
    if (EPI == 2) {
        sred[t] = (double)hs;
        __syncthreads();
        for (int o = 128; o > 0; o >>= 1) { if (t < o) sred[t] += sred[t + o]; __syncthreads(); }
        if (t == 0) part[blockIdx.y * gridDim.x + blockIdx.x] = sred[0];
    }
}

// ============================================================================
// Convert: P = softmax(S) row-wise, bf16 in/out; lse partials.
// ============================================================================
__global__ void __launch_bounds__(256) att_convert_b(
    const bf16* __restrict__ S, bf16* __restrict__ P, double* __restrict__ lse_part)
{
    const int bh = blockIdx.y;
    const int r0 = blockIdx.x * 16;
    const int t = threadIdx.x;
    const int rloc = t >> 4, lane = t & 15;
    const int row = r0 + rloc;
    const bf16* Sr = S + ((size_t)bh * Nn + row) * Nn;
    bf16* Pr = P + ((size_t)bh * Nn + row) * Nn;

    uint4 v[8];
    #pragma unroll
    for (int i = 0; i < 8; i++)
        v[i] = *(const uint4*)&Sr[(size_t)(i * 16 + lane) * 8];

    const __nv_bfloat162* hp = (const __nv_bfloat162*)v;
    float m = -CUDART_INF_F;
    #pragma unroll
    for (int j = 0; j < 32; j++) {
        float2 f = __bfloat1622float2(hp[j]);
        m = fmaxf(m, fmaxf(f.x, f.y));
    }
    #pragma unroll
    for (int o = 8; o > 0; o >>= 1) m = fmaxf(m, __shfl_xor_sync(0xffffffffu, m, o));

    float sum = 0.f;
    #pragma unroll
    for (int j = 0; j < 32; j++) {
        float2 f = __bfloat1622float2(hp[j]);
        sum += __expf(f.x - m) + __expf(f.y - m);
    }
    #pragma unroll
    for (int o = 8; o > 0; o >>= 1) sum += __shfl_xor_sync(0xffffffffu, sum, o);

    const float inv = 1.f / sum;
    #pragma unroll
    for (int i = 0; i < 8; i++) {
        uint4 w;
        bf16* wb = (bf16*)&w;
        const __nv_bfloat162* sp = (const __nv_bfloat162*)&v[i];
        #pragma unroll
        for (int j = 0; j < 4; j++) {
            float2 f = __bfloat1622float2(sp[j]);
            wb[2 * j + 0] = __float2bfloat16(__expf(f.x - m) * inv);
            wb[2 * j + 1] = __float2bfloat16(__expf(f.y - m) * inv);
        }
        *(uint4*)&Pr[(size_t)(i * 16 + lane) * 8] = w;
    }

    __shared__ double part[16];
    if (lane == 0) part[rloc] = (double)m + (double)logf(sum);
    __syncthreads();
    if (t == 0) {
        double s = 0.0;
        #pragma unroll
        for (int i = 0; i < 16; i++) s += part[i];
        lse_part[bh * (Nn / 16) + blockIdx.x] = s;
    }
}

// ============================================================================
// dQ-GEMM: dm[(b*N+n)][h*64+q] = bf16(-sum_m P'[n][m] * Kt[q][m])
// ============================================================================
#define DQ_STAGE 27648
__global__ void __launch_bounds__(256) att_dq_h(
    const bf16* __restrict__ P, const bf16* __restrict__ Kt, bf16* __restrict__ dm)
{
    extern __shared__ char dsm[];
    const uint32_t sbase = smem_u32(dsm);
    const int t = threadIdx.x, wid = t >> 5, lane = t & 31;
    const int bh = blockIdx.y, n0 = blockIdx.x * 128;
    const bf16* Ag = P + (size_t)bh * Nn * Nn;
    const bf16* Bg = Kt + (size_t)bh * QKd * Nn;

    float acc[8][4];
    #pragma unroll
    for (int i = 0; i < 8; i++)
        #pragma unroll
        for (int r = 0; r < 4; r++) acc[i][r] = 0.f;

    const int lrow = t >> 3, lseg = (t & 7) * 8;

    auto load = [&](int kb) {
        const uint32_t ab = sbase + (uint32_t)(kb & 1) * DQ_STAGE;
        const uint32_t bb = ab + 18432;
        const size_t kEl = (size_t)(kb << 6) + lseg;
        #pragma unroll
        for (int i = 0; i < 4; i++) {
            const int row = lrow + i * 32;
            asm volatile("cp.async.cg.shared.global [%0], [%1], 16;"
                :: "r"(ab + row * ROWSTR + lseg * 2), "l"(Ag + (size_t)(n0 + row) * Nn + kEl));
        }
        #pragma unroll
        for (int i = 0; i < 2; i++) {
            const int row = lrow + i * 32;
            asm volatile("cp.async.cg.shared.global [%0], [%1], 16;"
                :: "r"(bb + row * ROWSTR + lseg * 2), "l"(Bg + (size_t)row * Nn + kEl));
        }
        asm volatile("cp.async.commit_group;" ::: "memory");
    };

    load(0);
    for (int kb = 0; kb < 16; kb++) {
        if (kb < 15) { load(kb + 1); asm volatile("cp.async.wait_group 1;" ::: "memory"); }
        else         { asm volatile("cp.async.wait_group 0;" ::: "memory"); }
        __syncthreads();
        const uint32_t ab = sbase + (uint32_t)(kb & 1) * DQ_STAGE;
        const uint32_t bb = ab + 18432;
        const int acol = ((lane >> 4) * 8) * 2;
        const int arow = lane & 15;
        const int brow = (lane & 7) + ((lane >> 3) & 1) * 8;
        #pragma unroll
        for (int kk = 0; kk < 4; kk++) {
            const int kbyte = kk * 32 + acol;
            uint32_t a[4];
            asm volatile("ldmatrix.sync.aligned.m8n8.x4.shared.b16 {%0,%1,%2,%3}, [%4];"
                : "=r"(a[0]), "=r"(a[1]), "=r"(a[2]), "=r"(a[3])
                : "r"(ab + (wid * 16 + arow) * ROWSTR + kbyte));
            uint32_t b[8][2];
            #pragma unroll
            for (int nfp = 0; nfp < 4; nfp++) {
                uint32_t r0, r1, r2, r3;
                asm volatile("ldmatrix.sync.aligned.m8n8.x4.shared.b16 {%0,%1,%2,%3}, [%4];"
                    : "=r"(r0), "=r"(r1), "=r"(r2), "=r"(r3)
                    : "r"(bb + (nfp * 16 + brow) * ROWSTR + kbyte));
                b[nfp * 2 + 0][0] = r0; b[nfp * 2 + 0][1] = r2;
                b[nfp * 2 + 1][0] = r1; b[nfp * 2 + 1][1] = r3;
            }
            #pragma unroll
            for (int nf = 0; nf < 8; nf++)
                asm volatile(
                    "mma.sync.aligned.m16n8k16.row.col.f32.bf16.bf16.f32 "
                    "{%0,%1,%2,%3}, {%4,%5,%6,%7}, {%8,%9}, {%0,%1,%2,%3};"
                    : "+f"(acc[nf][0]), "+f"(acc[nf][1]), "+f"(acc[nf][2]), "+f"(acc[nf][3])
                    : "r"(a[0]), "r"(a[1]), "r"(a[2]), "r"(a[3]),
                      "r"(b[nf][0]), "r"(b[nf][1]));
        }
        __syncthreads();
    }
    const int gr = lane >> 2, gc = (lane & 3) * 2;
    const int b_ = bh >> 4, h_ = bh & 15;
    #pragma unroll
    for (int nf = 0; nf < 8; nf++) {
        const int col = nf * 8 + gc;
        #pragma unroll
        for (int half = 0; half < 2; half++) {
            const int n = n0 + wid * 16 + gr + half * 8;
            *(uint32_t*)&dm[((size_t)(b_ * 1024 + n)) * 2048 + h_ * 64 + col] =
                pack_bf2(-acc[nf][half * 2], -acc[nf][half * 2 + 1]);
        }
    }
}

// ============================================================================
// dK-GEMM: dm[(b*N+m)][1024 + h*64+q] = bf16(-sum_n P'[n][m] * Qt[q][n])
// ============================================================================
#define DK_ASTR 272
#define DK_STAGE 26624
__global__ void __launch_bounds__(256) att_dk_h(
    const bf16* __restrict__ P, const bf16* __restrict__ Qt, bf16* __restrict__ dm)
{
    extern __shared__ char dsm[];
    const uint32_t sbase = smem_u32(dsm);
    const int t = threadIdx.x, wid = t >> 5, lane = t & 31;
    const int bh = blockIdx.y, m0 = blockIdx.x * 128;
    const bf16* Ag = P + (size_t)bh * Nn * Nn;
    const bf16* Bg = Qt + (size_t)bh * QKd * Nn;

    float acc[8][4];
    #pragma unroll
    for (int i = 0; i < 8; i++)
        #pragma unroll
        for (int r = 0; r < 4; r++) acc[i][r] = 0.f;

    auto load = [&](int kb) {
        const uint32_t ab = sbase + (uint32_t)(kb & 1) * DK_STAGE;
        const uint32_t bb = ab + 17408;
        const int ar = t >> 4, aseg = (t & 15) * 8;
        #pragma unroll
        for (int i = 0; i < 4; i++) {
            const int row = ar + i * 16;
            asm volatile("cp.async.cg.shared.global [%0], [%1], 16;"
                :: "r"(ab + row * DK_ASTR + aseg * 2),
                   "l"(Ag + (size_t)((kb << 6) + row) * Nn + m0 + aseg));
        }
        const int br = t >> 3, bseg = (t & 7) * 8;
        #pragma unroll
        for (int i = 0; i < 2; i++) {
            const int row = br + i * 32;
            asm volatile("cp.async.cg.shared.global [%0], [%1], 16;"
                :: "r"(bb + row * ROWSTR + bseg * 2),
                   "l"(Bg + (size_t)row * Nn + (kb << 6) + bseg));
        }
        asm volatile("cp.async.commit_group;" ::: "memory");
    };

    load(0);
    for (int kb = 0; kb < 16; kb++) {
        if (kb < 15) { load(kb + 1); asm volatile("cp.async.wait_group 1;" ::: "memory"); }
        else         { asm volatile("cp.async.wait_group 0;" ::: "memory"); }
        __syncthreads();
        const uint32_t ab = sbase + (uint32_t)(kb & 1) * DK_STAGE;
        const uint32_t bb = ab + 17408;
        const int tl = lane >> 3;
        const int brow = (lane & 7) + ((lane >> 3) & 1) * 8;
        const int bcol = ((lane >> 4) * 8) * 2;
        #pragma unroll
        for (int kk = 0; kk < 4; kk++) {
            uint32_t a[4];
            const uint32_t ad = ab + (kk * 16 + (tl >> 1) * 8 + (lane & 7)) * DK_ASTR
                              + (wid * 16 + (tl & 1) * 8) * 2;
            asm volatile("ldmatrix.sync.aligned.m8n8.x4.trans.shared.b16 {%0,%1,%2,%3}, [%4];"
                : "=r"(a[0]), "=r"(a[1]), "=r"(a[2]), "=r"(a[3]) : "r"(ad));
            uint32_t b[8][2];
            const int kbyte = kk * 32 + bcol;
            #pragma unroll
            for (int nfp = 0; nfp < 4; nfp++) {
                uint32_t r0, r1, r2, r3;
                asm volatile("ldmatrix.sync.aligned.m8n8.x4.shared.b16 {%0,%1,%2,%3}, [%4];"
                    : "=r"(r0), "=r"(r1), "=r"(r2), "=r"(r3)
                    : "r"(bb + (nfp * 16 + brow) * ROWSTR + kbyte));
                b[nfp * 2 + 0][0] = r0; b[nfp * 2 + 0][1] = r2;
                b[nfp * 2 + 1][0] = r1; b[nfp * 2 + 1][1] = r3;
            }
            #pragma unroll
            for (int nf = 0; nf < 8; nf++)
                asm volatile(
                    "mma.sync.aligned.m16n8k16.row.col.f32.bf16.bf16.f32 "
                    "{%0,%1,%2,%3}, {%4,%5,%6,%7}, {%8,%9}, {%0,%1,%2,%3};"
                    : "+f"(acc[nf][0]), "+f"(acc[nf][1]), "+f"(acc[nf][2]), "+f"(acc[nf][3])
                    : "r"(a[0]), "r"(a[1]), "r"(a[2]), "r"(a[3]),
                      "r"(b[nf][0]), "r"(b[nf][1]));
        }
        __syncthreads();
    }
    const int gr = lane >> 2, gc = (lane & 3) * 2;
    const int b_ = bh >> 4, h_ = bh & 15;
    #pragma unroll
    for (int nf = 0; nf < 8; nf++) {
        const int col = nf * 8 + gc;
        #pragma unroll
        for (int half = 0; half < 2; half++) {
            const int m = m0 + wid * 16 + gr + half * 8;
            *(uint32_t*)&dm[((size_t)(b_ * 1024 + m)) * 2048 + 1024 + h_ * 64 + col] =
                pack_bf2(-acc[nf][half * 2], -acc[nf][half * 2 + 1]);
        }
    }
}

// ============================================================================
// Final energy: E = -(1/BETA) * sum(lse) - 0.5 * sum(h^2). Deterministic.
// ============================================================================
__global__ void energy_final(const double* __restrict__ lse_part,
                             const double* __restrict__ h2_part,
                             float* __restrict__ out)
{
    __shared__ double sm[256];
    int t = threadIdx.x;
    double s = 0.0;
    for (int i = t; i < BH * (Nn / 16); i += 256) s += lse_part[i];
    double s2 = 0.0;
    for (int i = t; i < (BNr / 128) * (HIDd / 128); i += 256) s2 += h2_part[i];
    sm[t] = -8.0 * s - 0.5 * s2;
    __syncthreads();
    for (int o = 128; o > 0; o >>= 1) { if (t < o) sm[t] += sm[t + o]; __syncthreads(); }
    if (t == 0) out[(size_t)BNr * Dd] = (float)sm[0];
}

// ============================================================================
// Host launcher
// ============================================================================
extern "C" void kernel_launch(void* const* d_in, const int* in_sizes, int n_in,
                              void* d_out, int out_size)
{
    const float* x    = (const float*)d_in[0];
    const float* Wq   = (const float*)d_in[1];
    const float* Wk   = (const float*)d_in[2];
    const float* Whop = (const float*)d_in[3];
    float* out = (float*)d_out;

    bf16 *pSb, *pP;
    double *pLse, *pH2;
    bf16 *px1, *px2, *pwq1, *pwk1, *pwt;
    bf16 *pwh1, *pwh2, *pwht1, *pwht2, *phb1, *phb2, *pdm;
    bf16 *pq1, *pk1, *pqt, *pkt;

    cudaGetSymbolAddress((void**)&pSb,  g_Sb);
    cudaGetSymbolAddress((void**)&pP,   g_P);
    cudaGetSymbolAddress((void**)&pLse, g_lse_part);
    cudaGetSymbolAddress((void**)&pH2,  g_h2_part);
    cudaGetSymbolAddress((void**)&px1,  g_x1);  cudaGetSymbolAddress((void**)&px2,  g_x2);
    cudaGetSymbolAddress((void**)&pwq1, g_wq1);
    cudaGetSymbolAddress((void**)&pwk1, g_wk1);
    cudaGetSymbolAddress((void**)&pwt,  g_wt);
    cudaGetSymbolAddress((void**)&pwh1, g_wh1); cudaGetSymbolAddress((void**)&pwh2, g_wh2);
    cudaGetSymbolAddress((void**)&pwht1,g_wht1);cudaGetSymbolAddress((void**)&pwht2,g_wht2);
    cudaGetSymbolAddress((void**)&phb1, g_hb1); cudaGetSymbolAddress((void**)&phb2, g_hb2);
    cudaGetSymbolAddress((void**)&pdm,  g_dm);
    cudaGetSymbolAddress((void**)&pq1,  g_q1);
    cudaGetSymbolAddress((void**)&pk1,  g_k1);
    cudaGetSymbolAddress((void**)&pqt,  g_qt);  cudaGetSymbolAddress((void**)&pkt,  g_kt);

    cudaFuncSetAttribute(tgemm<0,1>, cudaFuncAttributeMaxDynamicSharedMemorySize, TG_SMEM);
    cudaFuncSetAttribute(tgemm<0,3>, cudaFuncAttributeMaxDynamicSharedMemorySize, TG_SMEM);
    cudaFuncSetAttribute(tgemm<1,1>, cudaFuncAttributeMaxDynamicSharedMemorySize, TG_SMEM);
    cudaFuncSetAttribute(tgemm<2,3>, cudaFuncAttributeMaxDynamicSharedMemorySize, TG_SMEM);
    cudaFuncSetAttribute(tgemm<3,1>, cudaFuncAttributeMaxDynamicSharedMemorySize, TG_SMEM);
    cudaFuncSetAttribute(att_dq_h, cudaFuncAttributeMaxDynamicSharedMemorySize, 2 * DQ_STAGE);
    cudaFuncSetAttribute(att_dk_h, cudaFuncAttributeMaxDynamicSharedMemorySize, 2 * DK_STAGE);

    dim3 blk(256);

    // 0. input conversions (all coalesced)
    split_plain4<<<(BNr * Dd) / 1024, blk>>>(x, px1, px2);
    split_plain4<<<(Dd * HIDd) / 1024, blk>>>(Whop, pwh1, pwh2);
    cvt_plain4<<<(HQ * Dd) / 1024, blk>>>(Wq, pwq1);
    cvt_plain4<<<(HQ * Dd) / 1024, blk>>>(Wk, pwk1);
    trans_cvt1<<<dim3(Dd / 32, HQ / 32), blk>>>(Wq, pwt, HQ, Dd, 2048);          // WqT -> cols 0..1023
    trans_cvt1<<<dim3(Dd / 32, HQ / 32), blk>>>(Wk, pwt + 1024, HQ, Dd, 2048);   // WkT -> cols 1024..2047
    trans_split<<<dim3(HIDd / 32, Dd / 32), blk>>>(Whop, pwht1, pwht2, Dd, HIDd, Dd);

    // 1-2. Q,K projections (1-sweep HMMA) -> bf16 q1/k1 scattered [bh][n][qk]
    tgemm<1,1><<<dim3(HQ / 128, BNr / 128, 1), blk, TG_SMEM>>>(
        px1, nullptr, pwq1, nullptr, nullptr, HQ, Dd, 1.f, 0, pq1, nullptr, nullptr, 0, 0, 0);
    tgemm<1,1><<<dim3(HQ / 128, BNr / 128, 1), blk, TG_SMEM>>>(
        px1, nullptr, pwk1, nullptr, nullptr, HQ, Dd, 1.f, 0, pk1, nullptr, nullptr, 0, 0, 0);

    // 3. transposes for dq/dk B-operands
    trans_qk<<<dim3(Nn / 32, QKd / 32, BH), blk>>>(pq1, pk1, pqt, pkt);

    // 4. S = BETA * Q K^T (single-sweep batched HMMA, bf16 out)
    tgemm<3,1><<<dim3(Nn / 128, Nn / 128, BH), blk, TG_SMEM>>>(
        pq1, nullptr, pk1, nullptr, nullptr, Nn, QKd, BETA, 0, pSb, nullptr, nullptr,
        (size_t)Nn * QKd, (size_t)Nn * QKd, (size_t)Nn * Nn);

    // 5. softmax -> P bf16 + lse partials
    att_convert_b<<<dim3(Nn / 16, BH), blk>>>(pSb, pP, pLse);

    // 6. dQm, dKm -> merged bf16 [b*n][2048]
    att_dq_h<<<dim3(Nn / 128, BH), blk, 2 * DQ_STAGE>>>(pP, pkt, pdm);
    att_dk_h<<<dim3(Nn / 128, BH), blk, 2 * DK_STAGE>>>(pP, pqt, pdm);

    // 7. grad = dm @ [WqT|WkT]  (one K=2048 GEMM, writes out fully)
    tgemm<0,1><<<dim3(Dd / 128, BNr / 128, 1), blk, TG_SMEM>>>(
        pdm, nullptr, pwt, nullptr, out, Dd, 2048, 1.f, 0, nullptr, nullptr, nullptr, 0, 0, 0);

    // 8. Hb = relu(X @ W_hop) (3-sweep); h2 partials
    tgemm<2,3><<<dim3(HIDd / 128, BNr / 128, 1), blk, TG_SMEM>>>(
        px1, px2, pwht1, pwht2, nullptr, HIDd, Dd, 1.f, 0, phb1, phb2, pH2, 0, 0, 0);

    // 9. grad -= Hb @ W_hop^T (3-sweep)
    tgemm<0,3><<<dim3(Dd / 128, BNr / 128, 1), blk, TG_SMEM>>>(
        phb1, phb2, pwh1, pwh2, out, Dd, HIDd, -1.f, 1, nullptr, nullptr, nullptr, 0, 0, 0);

    // 10. energy scalar
    if (out_size > BNr * Dd)
        energy_final<<<1, 256>>>(pLse, pH2, out);
}